// round 2
// baseline (speedup 1.0000x reference)
#include <cuda_runtime.h>
#include <math.h>

// Problem constants
#define BB 2
#define SS 2048
#define FFDIM 1024
#define HH 16
#define DD 64
#define MROWS (BB * SS)      // 4096
#define N3 (3 * FFDIM)       // 3072

// Scratch (allocation-free rule: __device__ globals)
__device__ float g_qkv[(size_t)MROWS * N3];     // 48 MB: [4096, 3072]
__device__ float g_attn[(size_t)MROWS * FFDIM]; // 16 MB: [4096, 1024]
__device__ unsigned char g_mask[MROWS];         // canonical padding mask (1 = padded)

// ---------------------------------------------------------------------------
// Mask canonicalization: the harness delivers the bool mask as int32, float32,
// or uint8. Sniff the dtype from the first 1024 words (4 KB — safe for every
// candidate dtype) and write a canonical uint8 mask. Deterministic.
// ---------------------------------------------------------------------------
__global__ void mask_canon_kernel(const unsigned char* __restrict__ raw)
{
    __shared__ unsigned s_flags;
    const unsigned* w = (const unsigned*)raw;
    const int tid = threadIdx.x;            // 256 threads, 1 block

    if (tid == 0) s_flags = 0;
    __syncthreads();

    unsigned flags = 0;
    for (int i = tid; i < 1024; i += 256) {
        unsigned v = w[i];
        if (v > 1u) flags |= 1u;                         // not int32 {0,1}
        if (v != 0u && v != 0x3f800000u) flags |= 2u;    // not float32 {0,1}
    }
    atomicOr(&s_flags, flags);
    __syncthreads();
    const unsigned f = s_flags;

    if (!(f & 1u)) {
        // int32 {0,1}
        for (int i = tid; i < MROWS; i += 256)
            g_mask[i] = (w[i] != 0u) ? 1 : 0;
    } else if (!(f & 2u)) {
        // float32 {0.0, 1.0}
        const float* fp = (const float*)raw;
        for (int i = tid; i < MROWS; i += 256)
            g_mask[i] = (fp[i] != 0.f) ? 1 : 0;
    } else {
        // uint8/bool bytes
        for (int i = tid; i < MROWS; i += 256)
            g_mask[i] = (raw[i] != 0) ? 1 : 0;
    }
}

// ---------------------------------------------------------------------------
// SGEMM: C[M,N] = A[M,K] @ W[K,N] + bias[N]  (+ residual R[M,N] if RES)
// BM=BN=128, BK=16, 256 threads, 8x8 register tile per thread.
// ---------------------------------------------------------------------------
template <bool RES>
__global__ __launch_bounds__(256) void sgemm_kernel(
    const float* __restrict__ A, const float* __restrict__ W,
    const float* __restrict__ bias, const float* __restrict__ R,
    float* __restrict__ C, int M, int N, int K)
{
    const int BM = 128, BN = 128, BK = 16;
    __shared__ float As[BK][BM];   // transposed A tile
    __shared__ float Ws[BK][BN];

    const int tid = threadIdx.x;
    const int m0 = blockIdx.y * BM;
    const int n0 = blockIdx.x * BN;
    const int tx = tid & 15;
    const int ty = tid >> 4;

    float acc[8][8];
#pragma unroll
    for (int i = 0; i < 8; i++)
#pragma unroll
        for (int j = 0; j < 8; j++) acc[i][j] = 0.f;

    for (int k0 = 0; k0 < K; k0 += BK) {
#pragma unroll
        for (int i = 0; i < 2; i++) {
            int l = tid * 2 + i;
            int row = l >> 2;
            int c4  = l & 3;
            float4 v = *(const float4*)(A + (size_t)(m0 + row) * K + k0 + c4 * 4);
            As[c4 * 4 + 0][row] = v.x;
            As[c4 * 4 + 1][row] = v.y;
            As[c4 * 4 + 2][row] = v.z;
            As[c4 * 4 + 3][row] = v.w;
        }
#pragma unroll
        for (int i = 0; i < 2; i++) {
            int l = tid + i * 256;
            int row = l >> 5;
            int c4  = l & 31;
            float4 v = *(const float4*)(W + (size_t)(k0 + row) * N + n0 + c4 * 4);
            *(float4*)&Ws[row][c4 * 4] = v;
        }
        __syncthreads();

#pragma unroll
        for (int kk = 0; kk < BK; kk++) {
            float ra[8], rb[8];
            *(float4*)&ra[0] = *(const float4*)&As[kk][ty * 8];
            *(float4*)&ra[4] = *(const float4*)&As[kk][ty * 8 + 4];
            *(float4*)&rb[0] = *(const float4*)&Ws[kk][tx * 8];
            *(float4*)&rb[4] = *(const float4*)&Ws[kk][tx * 8 + 4];
#pragma unroll
            for (int i = 0; i < 8; i++)
#pragma unroll
                for (int j = 0; j < 8; j++)
                    acc[i][j] += ra[i] * rb[j];
        }
        __syncthreads();
    }

    float bv[8];
    *(float4*)&bv[0] = *(const float4*)(bias + n0 + tx * 8);
    *(float4*)&bv[4] = *(const float4*)(bias + n0 + tx * 8 + 4);
#pragma unroll
    for (int i = 0; i < 8; i++) {
        size_t off = (size_t)(m0 + ty * 8 + i) * N + n0 + tx * 8;
        float4 o1, o2;
        o1.x = acc[i][0] + bv[0]; o1.y = acc[i][1] + bv[1];
        o1.z = acc[i][2] + bv[2]; o1.w = acc[i][3] + bv[3];
        o2.x = acc[i][4] + bv[4]; o2.y = acc[i][5] + bv[5];
        o2.z = acc[i][6] + bv[6]; o2.w = acc[i][7] + bv[7];
        if (RES) {
            float4 r1 = *(const float4*)(R + off);
            float4 r2 = *(const float4*)(R + off + 4);
            o1.x += r1.x; o1.y += r1.y; o1.z += r1.z; o1.w += r1.w;
            o2.x += r2.x; o2.y += r2.y; o2.z += r2.z; o2.w += r2.w;
        }
        *(float4*)(C + off)     = o1;
        *(float4*)(C + off + 4) = o2;
    }
}

// ---------------------------------------------------------------------------
// Flash attention (fp32): grid (S/128, H, B), 128 threads, 1 thread = 1 query
// row. K/V tiles of 64 keys staged in smem. Online softmax with lazy rescale.
// Padded keys skipped uniformly per warp via canonical g_mask.
// ---------------------------------------------------------------------------
#define KSTRIDE 68   // 64 + 4 pad

__global__ __launch_bounds__(128) void attn_kernel()
{
    __shared__ float ks[64 * KSTRIDE];
    __shared__ float vs[64 * KSTRIDE];
    __shared__ unsigned char pms[64];

    const int qb  = (int)gridDim.x - 1 - (int)blockIdx.x;  // big work first
    const int h   = blockIdx.y;
    const int b   = blockIdx.z;
    const int tid = threadIdx.x;
    const int q   = qb * 128 + tid;

    float qv[64];
    {
        const float* qrow = g_qkv + (size_t)(b * SS + q) * N3 + h * DD;
#pragma unroll
        for (int d4 = 0; d4 < 16; d4++) {
            float4 v = *(const float4*)(qrow + d4 * 4);
            qv[4 * d4 + 0] = v.x; qv[4 * d4 + 1] = v.y;
            qv[4 * d4 + 2] = v.z; qv[4 * d4 + 3] = v.w;
        }
    }

    float ov[64];
#pragma unroll
    for (int d = 0; d < 64; d++) ov[d] = 0.f;
    float m = -INFINITY, l = 0.f;

    const int warp_qmax = qb * 128 + ((tid >> 5) << 5) + 31;
    const int ntiles = 2 * qb + 2;
    const float* kbase = g_qkv + (size_t)(b * SS) * N3 + FFDIM + h * DD;
    const float* vbase = g_qkv + (size_t)(b * SS) * N3 + 2 * FFDIM + h * DD;

    for (int kt = 0; kt < ntiles; kt++) {
        __syncthreads();
#pragma unroll
        for (int it = 0; it < 8; it++) {
            int idx = it * 128 + tid;
            int row = idx >> 4;
            int c4  = idx & 15;
            size_t g = (size_t)(kt * 64 + row) * N3 + c4 * 4;
            *(float4*)&ks[row * KSTRIDE + c4 * 4] = *(const float4*)(kbase + g);
            *(float4*)&vs[row * KSTRIDE + c4 * 4] = *(const float4*)(vbase + g);
        }
        if (tid < 64) pms[tid] = g_mask[b * SS + kt * 64 + tid];
        __syncthreads();

        if (kt * 64 > warp_qmax) continue;

        for (int j = 0; j < 64; j++) {
            if (pms[j]) continue;                  // uniform across warp
            const int kg = kt * 64 + j;

            float s0 = 0.f, s1 = 0.f, s2 = 0.f, s3 = 0.f;
            const float* kr = &ks[j * KSTRIDE];
#pragma unroll
            for (int d4 = 0; d4 < 16; d4++) {
                float4 kk = *(const float4*)(kr + d4 * 4);
                s0 += qv[4 * d4 + 0] * kk.x;
                s1 += qv[4 * d4 + 1] * kk.y;
                s2 += qv[4 * d4 + 2] * kk.z;
                s3 += qv[4 * d4 + 3] * kk.w;
            }
            float s = (s0 + s1 + s2 + s3) * 0.125f;

            float p = 0.f;
            if (kg <= q) {
                if (s > m) {
                    float c = __expf(m - s);
                    l *= c;
#pragma unroll
                    for (int d = 0; d < 64; d++) ov[d] *= c;
                    m = s;
                    p = 1.f;
                } else {
                    p = __expf(s - m);
                }
                l += p;
            }
            if (__all_sync(0xffffffffu, p == 0.f)) continue;

            const float* vr = &vs[j * KSTRIDE];
#pragma unroll
            for (int d4 = 0; d4 < 16; d4++) {
                float4 vv = *(const float4*)(vr + d4 * 4);
                ov[4 * d4 + 0] += p * vv.x;
                ov[4 * d4 + 1] += p * vv.y;
                ov[4 * d4 + 2] += p * vv.z;
                ov[4 * d4 + 3] += p * vv.w;
            }
        }
    }

    const float inv = (l > 0.f) ? (1.f / l) : 0.f;
    float* orow = g_attn + (size_t)(b * SS + q) * FFDIM + h * DD;
#pragma unroll
    for (int d4 = 0; d4 < 16; d4++) {
        float4 o;
        o.x = ov[4 * d4 + 0] * inv; o.y = ov[4 * d4 + 1] * inv;
        o.z = ov[4 * d4 + 2] * inv; o.w = ov[4 * d4 + 3] * inv;
        *(float4*)(orow + d4 * 4) = o;
    }
}

// ---------------------------------------------------------------------------
// Launch: qkv = x@w_qkv + b_qkv ; attn ; out = x + attn@w_out + b_out
// ---------------------------------------------------------------------------
extern "C" void kernel_launch(void* const* d_in, const int* in_sizes, int n_in,
                              void* d_out, int out_size)
{
    const float*         x      = (const float*)d_in[0];
    const unsigned char* pmask  = (const unsigned char*)d_in[1];
    const float*         w_qkv  = (const float*)d_in[2];
    const float*         b_qkv  = (const float*)d_in[3];
    const float*         w_out  = (const float*)d_in[4];
    const float*         b_out  = (const float*)d_in[5];
    float*               out    = (float*)d_out;

    float* qkv = nullptr;
    float* attn = nullptr;
    cudaGetSymbolAddress((void**)&qkv,  g_qkv);
    cudaGetSymbolAddress((void**)&attn, g_attn);

    mask_canon_kernel<<<1, 256>>>(pmask);

    // GEMM1: [4096,1024] @ [1024,3072] + b_qkv -> g_qkv
    {
        dim3 grid(N3 / 128, MROWS / 128);
        sgemm_kernel<false><<<grid, 256>>>(x, w_qkv, b_qkv, nullptr, qkv,
                                           MROWS, N3, FFDIM);
    }
    // Attention: g_qkv -> g_attn
    {
        dim3 grid(SS / 128, HH, BB);
        attn_kernel<<<grid, 128>>>();
    }
    // GEMM2: x + [4096,1024] @ [1024,1024] + b_out -> out
    {
        dim3 grid(FFDIM / 128, MROWS / 128);
        sgemm_kernel<true><<<grid, 256>>>(attn, w_out, b_out, x, out,
                                          MROWS, FFDIM, FFDIM);
    }
}

// round 5
// speedup vs baseline: 1.1677x; 1.1677x over previous
#include <cuda_runtime.h>
#include <math.h>
#include <cstdint>

// Problem constants
#define BB 2
#define SS 2048
#define FFDIM 1024
#define HH 16
#define DD 64
#define MROWS (BB * SS)      // 4096
#define N3 (3 * FFDIM)       // 3072

// Scratch
__device__ float g_qkv[(size_t)MROWS * N3];     // 48 MB
__device__ float g_attn[(size_t)MROWS * FFDIM]; // 16 MB
__device__ unsigned char g_mask[MROWS];

__device__ __forceinline__ uint32_t f2tf32(float v) {
    uint32_t o;
    asm("cvt.rna.tf32.f32 %0, %1;" : "=r"(o) : "f"(v));
    return o;
}

// ============================ mask canonicalization ============================
__global__ void mask_canon_kernel(const unsigned char* __restrict__ raw)
{
    __shared__ unsigned s_flags;
    const unsigned* w = (const unsigned*)raw;
    const int tid = threadIdx.x;
    if (tid == 0) s_flags = 0;
    __syncthreads();
    unsigned flags = 0;
    for (int i = tid; i < 1024; i += 256) {
        unsigned v = w[i];
        if (v > 1u) flags |= 1u;
        if (v != 0u && v != 0x3f800000u) flags |= 2u;
    }
    atomicOr(&s_flags, flags);
    __syncthreads();
    const unsigned f = s_flags;
    if (!(f & 1u)) {
        for (int i = tid; i < MROWS; i += 256) g_mask[i] = (w[i] != 0u) ? 1 : 0;
    } else if (!(f & 2u)) {
        const float* fp = (const float*)raw;
        for (int i = tid; i < MROWS; i += 256) g_mask[i] = (fp[i] != 0.f) ? 1 : 0;
    } else {
        for (int i = tid; i < MROWS; i += 256) g_mask[i] = (raw[i] != 0) ? 1 : 0;
    }
}

// ============================ tf32 mma.sync GEMM ============================
// C[M,N] = A[M,K] @ W[K,N] + bias (+R).
// 256 threads = 8 warps (2 m x 4 n), warp tile 64x32, block tile 128x128, BK=32.
// SMEM: As[2][128][33] + Bs[2][128][33] floats (tf32 bits), dynamic.
#define ASTRIDE 33
#define BUFSZ (128 * ASTRIDE)          // floats per buffer

template <bool RES>
__global__ __launch_bounds__(256) void tf32_mma_gemm(
    const float* __restrict__ A, const float* __restrict__ W,
    const float* __restrict__ bias, const float* __restrict__ R,
    float* __restrict__ C, int N, int K)
{
    extern __shared__ float sm[];     // [0,2*BUFSZ): As, [2*BUFSZ,4*BUFSZ): Bs
    const int tid  = threadIdx.x;
    const int wid  = tid >> 5;
    const int lane = tid & 31;
    const int gid  = lane >> 2;       // 0..7
    const int tig  = lane & 3;        // 0..3
    const int warp_m = wid & 1;       // 2
    const int warp_n = wid >> 1;      // 4
    const int m0 = blockIdx.y * 128;
    const int n0 = blockIdx.x * 128;
    const int mbase = warp_m * 64;
    const int nbase = warp_n * 32;

    float acc[4][4][4];
#pragma unroll
    for (int i = 0; i < 4; i++)
#pragma unroll
        for (int j = 0; j < 4; j++)
#pragma unroll
            for (int c = 0; c < 4; c++) acc[i][j][c] = 0.f;

    const int nch = K >> 5;

    // ---- prologue: stage chunk 0 into buffer 0 ----
#pragma unroll
    for (int it = 0; it < 4; it++) {
        int l = tid + it * 256;
        int row = l >> 3, c4 = l & 7;
        float4 v = *(const float4*)(A + (size_t)(m0 + row) * K + c4 * 4);
        float* d = &sm[row * ASTRIDE + c4 * 4];
        d[0] = __uint_as_float(f2tf32(v.x));
        d[1] = __uint_as_float(f2tf32(v.y));
        d[2] = __uint_as_float(f2tf32(v.z));
        d[3] = __uint_as_float(f2tf32(v.w));
    }
#pragma unroll
    for (int it = 0; it < 4; it++) {
        int l = tid + it * 256;
        int k = l >> 5, c4 = l & 31;
        float4 v = *(const float4*)(W + (size_t)k * N + n0 + c4 * 4);
        float* base = &sm[2 * BUFSZ + (c4 * 4) * ASTRIDE + k];
        base[0 * ASTRIDE] = __uint_as_float(f2tf32(v.x));
        base[1 * ASTRIDE] = __uint_as_float(f2tf32(v.y));
        base[2 * ASTRIDE] = __uint_as_float(f2tf32(v.z));
        base[3 * ASTRIDE] = __uint_as_float(f2tf32(v.w));
    }
    __syncthreads();

    for (int ch = 0; ch < nch; ch++) {
        const int buf = ch & 1;
        const bool more = (ch + 1) < nch;
        float4 pa[4], pb[4];
        if (more) {
            const int kn = (ch + 1) * 32;
#pragma unroll
            for (int it = 0; it < 4; it++) {
                int l = tid + it * 256;
                int row = l >> 3, c4 = l & 7;
                pa[it] = *(const float4*)(A + (size_t)(m0 + row) * K + kn + c4 * 4);
            }
#pragma unroll
            for (int it = 0; it < 4; it++) {
                int l = tid + it * 256;
                int k = l >> 5, c4 = l & 31;
                pb[it] = *(const float4*)(W + (size_t)(kn + k) * N + n0 + c4 * 4);
            }
        }

        // ---- compute 4 k-steps of 8 ----
        const float* As = &sm[buf * BUFSZ];
        const float* Bs = &sm[2 * BUFSZ + buf * BUFSZ];
#pragma unroll
        for (int ks = 0; ks < 4; ks++) {
            const int k = ks * 8;
            uint32_t af[4][4], bf[4][2];
#pragma unroll
            for (int mf = 0; mf < 4; mf++) {
                const int r0 = mbase + mf * 16 + gid;
                af[mf][0] = __float_as_uint(As[r0 * ASTRIDE + k + tig]);
                af[mf][1] = __float_as_uint(As[(r0 + 8) * ASTRIDE + k + tig]);
                af[mf][2] = __float_as_uint(As[r0 * ASTRIDE + k + tig + 4]);
                af[mf][3] = __float_as_uint(As[(r0 + 8) * ASTRIDE + k + tig + 4]);
            }
#pragma unroll
            for (int nf = 0; nf < 4; nf++) {
                const int n = nbase + nf * 8 + gid;
                bf[nf][0] = __float_as_uint(Bs[n * ASTRIDE + k + tig]);
                bf[nf][1] = __float_as_uint(Bs[n * ASTRIDE + k + tig + 4]);
            }
#pragma unroll
            for (int mf = 0; mf < 4; mf++)
#pragma unroll
                for (int nf = 0; nf < 4; nf++) {
                    asm volatile(
                        "mma.sync.aligned.m16n8k8.row.col.f32.tf32.tf32.f32 "
                        "{%0,%1,%2,%3}, {%4,%5,%6,%7}, {%8,%9}, {%0,%1,%2,%3};"
                        : "+f"(acc[mf][nf][0]), "+f"(acc[mf][nf][1]),
                          "+f"(acc[mf][nf][2]), "+f"(acc[mf][nf][3])
                        : "r"(af[mf][0]), "r"(af[mf][1]), "r"(af[mf][2]), "r"(af[mf][3]),
                          "r"(bf[nf][0]), "r"(bf[nf][1]));
                }
        }

        if (more) {
            __syncthreads();
            float* Ad = &sm[(buf ^ 1) * BUFSZ];
            float* Bd = &sm[2 * BUFSZ + (buf ^ 1) * BUFSZ];
#pragma unroll
            for (int it = 0; it < 4; it++) {
                int l = tid + it * 256;
                int row = l >> 3, c4 = l & 7;
                float* d = &Ad[row * ASTRIDE + c4 * 4];
                d[0] = __uint_as_float(f2tf32(pa[it].x));
                d[1] = __uint_as_float(f2tf32(pa[it].y));
                d[2] = __uint_as_float(f2tf32(pa[it].z));
                d[3] = __uint_as_float(f2tf32(pa[it].w));
            }
#pragma unroll
            for (int it = 0; it < 4; it++) {
                int l = tid + it * 256;
                int k = l >> 5, c4 = l & 31;
                float* base = &Bd[(c4 * 4) * ASTRIDE + k];
                base[0 * ASTRIDE] = __uint_as_float(f2tf32(pb[it].x));
                base[1 * ASTRIDE] = __uint_as_float(f2tf32(pb[it].y));
                base[2 * ASTRIDE] = __uint_as_float(f2tf32(pb[it].z));
                base[3 * ASTRIDE] = __uint_as_float(f2tf32(pb[it].w));
            }
            __syncthreads();
        }
    }

    // ---- epilogue ----
#pragma unroll
    for (int mf = 0; mf < 4; mf++) {
        const int rr = m0 + mbase + mf * 16 + gid;
#pragma unroll
        for (int nf = 0; nf < 4; nf++) {
            const int cc = n0 + nbase + nf * 8 + 2 * tig;
            const float b0 = bias[cc], b1 = bias[cc + 1];
            size_t o0 = (size_t)rr * N + cc;
            size_t o1 = (size_t)(rr + 8) * N + cc;
            float2 v0, v1;
            v0.x = acc[mf][nf][0] + b0; v0.y = acc[mf][nf][1] + b1;
            v1.x = acc[mf][nf][2] + b0; v1.y = acc[mf][nf][3] + b1;
            if (RES) {
                float2 r0 = *(const float2*)(R + o0);
                float2 r1 = *(const float2*)(R + o1);
                v0.x += r0.x; v0.y += r0.y;
                v1.x += r1.x; v1.y += r1.y;
            }
            *(float2*)(C + o0) = v0;
            *(float2*)(C + o1) = v1;
        }
    }
}

// ============================ flash attention (fp32, unchanged) ============================
#define KSTRIDE 68

__global__ __launch_bounds__(128) void attn_kernel()
{
    __shared__ float ks[64 * KSTRIDE];
    __shared__ float vs[64 * KSTRIDE];
    __shared__ unsigned char pms[64];

    const int qb  = (int)gridDim.x - 1 - (int)blockIdx.x;
    const int h   = blockIdx.y;
    const int b   = blockIdx.z;
    const int tid = threadIdx.x;
    const int q   = qb * 128 + tid;

    float qv[64];
    {
        const float* qrow = g_qkv + (size_t)(b * SS + q) * N3 + h * DD;
#pragma unroll
        for (int d4 = 0; d4 < 16; d4++) {
            float4 v = *(const float4*)(qrow + d4 * 4);
            qv[4 * d4 + 0] = v.x; qv[4 * d4 + 1] = v.y;
            qv[4 * d4 + 2] = v.z; qv[4 * d4 + 3] = v.w;
        }
    }

    float ov[64];
#pragma unroll
    for (int d = 0; d < 64; d++) ov[d] = 0.f;
    float m = -INFINITY, l = 0.f;

    const int warp_qmax = qb * 128 + ((tid >> 5) << 5) + 31;
    const int ntiles = 2 * qb + 2;
    const float* kbase = g_qkv + (size_t)(b * SS) * N3 + FFDIM + h * DD;
    const float* vbase = g_qkv + (size_t)(b * SS) * N3 + 2 * FFDIM + h * DD;

    for (int kt = 0; kt < ntiles; kt++) {
        __syncthreads();
#pragma unroll
        for (int it = 0; it < 8; it++) {
            int idx = it * 128 + tid;
            int row = idx >> 4;
            int c4  = idx & 15;
            size_t g = (size_t)(kt * 64 + row) * N3 + c4 * 4;
            *(float4*)&ks[row * KSTRIDE + c4 * 4] = *(const float4*)(kbase + g);
            *(float4*)&vs[row * KSTRIDE + c4 * 4] = *(const float4*)(vbase + g);
        }
        if (tid < 64) pms[tid] = g_mask[b * SS + kt * 64 + tid];
        __syncthreads();

        if (kt * 64 > warp_qmax) continue;

        for (int j = 0; j < 64; j++) {
            if (pms[j]) continue;
            const int kg = kt * 64 + j;

            float s0 = 0.f, s1 = 0.f, s2 = 0.f, s3 = 0.f;
            const float* kr = &ks[j * KSTRIDE];
#pragma unroll
            for (int d4 = 0; d4 < 16; d4++) {
                float4 kk = *(const float4*)(kr + d4 * 4);
                s0 += qv[4 * d4 + 0] * kk.x;
                s1 += qv[4 * d4 + 1] * kk.y;
                s2 += qv[4 * d4 + 2] * kk.z;
                s3 += qv[4 * d4 + 3] * kk.w;
            }
            float s = (s0 + s1 + s2 + s3) * 0.125f;

            float p = 0.f;
            if (kg <= q) {
                if (s > m) {
                    float c = __expf(m - s);
                    l *= c;
#pragma unroll
                    for (int d = 0; d < 64; d++) ov[d] *= c;
                    m = s;
                    p = 1.f;
                } else {
                    p = __expf(s - m);
                }
                l += p;
            }
            if (__all_sync(0xffffffffu, p == 0.f)) continue;

            const float* vr = &vs[j * KSTRIDE];
#pragma unroll
            for (int d4 = 0; d4 < 16; d4++) {
                float4 vv = *(const float4*)(vr + d4 * 4);
                ov[4 * d4 + 0] += p * vv.x;
                ov[4 * d4 + 1] += p * vv.y;
                ov[4 * d4 + 2] += p * vv.z;
                ov[4 * d4 + 3] += p * vv.w;
            }
        }
    }

    const float inv = (l > 0.f) ? (1.f / l) : 0.f;
    float* orow = g_attn + (size_t)(b * SS + q) * FFDIM + h * DD;
#pragma unroll
    for (int d4 = 0; d4 < 16; d4++) {
        float4 o;
        o.x = ov[4 * d4 + 0] * inv; o.y = ov[4 * d4 + 1] * inv;
        o.z = ov[4 * d4 + 2] * inv; o.w = ov[4 * d4 + 3] * inv;
        *(float4*)(orow + d4 * 4) = o;
    }
}

// ============================ launch ============================
#define GEMM_SMEM (4 * BUFSZ * (int)sizeof(float))   // 67584 bytes

extern "C" void kernel_launch(void* const* d_in, const int* in_sizes, int n_in,
                              void* d_out, int out_size)
{
    const float*         x      = (const float*)d_in[0];
    const unsigned char* pmask  = (const unsigned char*)d_in[1];
    const float*         w_qkv  = (const float*)d_in[2];
    const float*         b_qkv  = (const float*)d_in[3];
    const float*         w_out  = (const float*)d_in[4];
    const float*         b_out  = (const float*)d_in[5];
    float*               out    = (float*)d_out;

    float* qkv = nullptr;
    float* attn = nullptr;
    cudaGetSymbolAddress((void**)&qkv,  g_qkv);
    cudaGetSymbolAddress((void**)&attn, g_attn);

    cudaFuncSetAttribute(tf32_mma_gemm<false>,
                         cudaFuncAttributeMaxDynamicSharedMemorySize, GEMM_SMEM);
    cudaFuncSetAttribute(tf32_mma_gemm<true>,
                         cudaFuncAttributeMaxDynamicSharedMemorySize, GEMM_SMEM);

    mask_canon_kernel<<<1, 256>>>(pmask);

    // GEMM1: [4096,1024] @ [1024,3072] + b_qkv -> g_qkv
    {
        dim3 grid(N3 / 128, MROWS / 128);
        tf32_mma_gemm<false><<<grid, 256, GEMM_SMEM>>>(x, w_qkv, b_qkv, nullptr,
                                                       qkv, N3, FFDIM);
    }
    // Attention
    {
        dim3 grid(SS / 128, HH, BB);
        attn_kernel<<<grid, 128>>>();
    }
    // GEMM2: x + [4096,1024] @ [1024,1024] + b_out -> out
    {
        dim3 grid(FFDIM / 128, MROWS / 128);
        tf32_mma_gemm<true><<<grid, 256, GEMM_SMEM>>>(attn, w_out, b_out, x,
                                                      out, FFDIM, FFDIM);
    }
}

// round 6
// speedup vs baseline: 1.6641x; 1.4252x over previous
#include <cuda_runtime.h>
#include <math.h>
#include <cstdint>

// Problem constants
#define BB 2
#define SS 2048
#define FFDIM 1024
#define HH 16
#define DD 64
#define MROWS (BB * SS)      // 4096
#define N3 (3 * FFDIM)       // 3072

// Scratch
__device__ float g_qkv[(size_t)MROWS * N3];     // 48 MB
__device__ float g_attn[(size_t)MROWS * FFDIM]; // 16 MB
__device__ unsigned char g_mask[MROWS];

// ============================ helpers ============================
__device__ __forceinline__ uint32_t smem_u32(const void* p) {
    uint32_t a;
    asm("{ .reg .u64 t; cvta.to.shared.u64 t, %1; cvt.u32.u64 %0, t; }" : "=r"(a) : "l"(p));
    return a;
}
__device__ __forceinline__ void cp_async16(uint32_t dst, const void* src) {
    asm volatile("cp.async.cg.shared.global [%0], [%1], 16;" :: "r"(dst), "l"(src));
}
#define CP_COMMIT() asm volatile("cp.async.commit_group;" ::: "memory")
#define CP_WAIT2()  asm volatile("cp.async.wait_group 2;" ::: "memory")
#define CP_WAIT0()  asm volatile("cp.async.wait_group 0;" ::: "memory")

// ============================ mask canonicalization ============================
__global__ void mask_canon_kernel(const unsigned char* __restrict__ raw)
{
    __shared__ unsigned s_flags;
    const unsigned* w = (const unsigned*)raw;
    const int tid = threadIdx.x;
    if (tid == 0) s_flags = 0;
    __syncthreads();
    unsigned flags = 0;
    for (int i = tid; i < 1024; i += 256) {
        unsigned v = w[i];
        if (v > 1u) flags |= 1u;
        if (v != 0u && v != 0x3f800000u) flags |= 2u;
    }
    atomicOr(&s_flags, flags);
    __syncthreads();
    const unsigned f = s_flags;
    if (!(f & 1u)) {
        for (int i = tid; i < MROWS; i += 256) g_mask[i] = (w[i] != 0u) ? 1 : 0;
    } else if (!(f & 2u)) {
        const float* fp = (const float*)raw;
        for (int i = tid; i < MROWS; i += 256) g_mask[i] = (fp[i] != 0.f) ? 1 : 0;
    } else {
        for (int i = tid; i < MROWS; i += 256) g_mask[i] = (raw[i] != 0) ? 1 : 0;
    }
}

// ============================ tf32 mma.sync GEMM v2 ============================
// C[M,N] = A[M,K] @ W[K,N] + bias (+R).
// 128 threads = 4 warps (2m x 2n), warp tile 64x64, block tile 128x128, BK=32.
// cp.async 3-stage pipeline; raw f32 fed to tf32 mma (HW truncation).
#define BKC 32
#define STAGES 3
#define AS_STRIDE 36                     // 32 + 4 pad
#define BS_STRIDE 132                    // 128 + 4 pad
#define A_STAGE (128 * AS_STRIDE)        // 4608 floats
#define B_STAGE (BKC * BS_STRIDE)        // 4224 floats
#define STAGE_FLOATS (A_STAGE + B_STAGE) // 8832 floats
#define GEMM_SMEM (STAGES * STAGE_FLOATS * 4)  // 105984 bytes

template <bool RES>
__global__ __launch_bounds__(128, 2) void tf32_mma_gemm(
    const float* __restrict__ A, const float* __restrict__ W,
    const float* __restrict__ bias, const float* __restrict__ R,
    float* __restrict__ C, int N, int K)
{
    extern __shared__ float sm[];
    const uint32_t smb = smem_u32(sm);
    const int tid  = threadIdx.x;
    const int wid  = tid >> 5;
    const int lane = tid & 31;
    const int gid  = lane >> 2;       // 0..7
    const int tig  = lane & 3;        // 0..3
    const int mbase = (wid & 1) * 64;
    const int nbase = (wid >> 1) * 64;
    const int m0 = blockIdx.y * 128;
    const int n0 = blockIdx.x * 128;

    const int arow = tid >> 3, ac4 = tid & 7;      // A: 16 rows per it-step? (see loop)
    const int bkr  = tid >> 5, bc4 = tid & 31;     // B

    const float* Abase = A + (size_t)m0 * K;
    const float* Bbase = W + n0;

    // stage issuer: chunk kc into buffer buf
    auto issue_stage = [&](int kc, int buf) {
        const float* Asrc = Abase + kc * BKC;
        uint32_t ab = smb + (uint32_t)(buf * STAGE_FLOATS) * 4u;
#pragma unroll
        for (int it = 0; it < 8; it++) {
            int row = arow + it * 16;
            cp_async16(ab + (uint32_t)(row * AS_STRIDE + ac4 * 4) * 4u,
                       Asrc + (size_t)row * K + ac4 * 4);
        }
        const float* Bsrc = Bbase + (size_t)(kc * BKC) * N;
        uint32_t bb = smb + (uint32_t)(buf * STAGE_FLOATS + A_STAGE) * 4u;
#pragma unroll
        for (int it = 0; it < 8; it++) {
            int kr = bkr + it * 4;
            cp_async16(bb + (uint32_t)(kr * BS_STRIDE + bc4 * 4) * 4u,
                       Bsrc + (size_t)kr * N + bc4 * 4);
        }
    };

    float acc[4][8][4];
#pragma unroll
    for (int i = 0; i < 4; i++)
#pragma unroll
        for (int j = 0; j < 8; j++)
#pragma unroll
            for (int c = 0; c < 4; c++) acc[i][j][c] = 0.f;

    const int nch = K / BKC;   // 32

    issue_stage(0, 0); CP_COMMIT();
    issue_stage(1, 1); CP_COMMIT();

    for (int ch = 0; ch < nch; ch++) {
        if (ch + 2 < nch) issue_stage(ch + 2, (ch + 2) % STAGES);
        CP_COMMIT();
        CP_WAIT2();
        __syncthreads();

        const float* As = sm + (ch % STAGES) * STAGE_FLOATS;
        const float* Bs = As + A_STAGE;
#pragma unroll
        for (int ks = 0; ks < 4; ks++) {
            const int k = ks * 8;
            uint32_t af[4][4], bf[8][2];
#pragma unroll
            for (int mf = 0; mf < 4; mf++) {
                const int r0 = mbase + mf * 16 + gid;
                af[mf][0] = __float_as_uint(As[r0 * AS_STRIDE + k + tig]);
                af[mf][1] = __float_as_uint(As[(r0 + 8) * AS_STRIDE + k + tig]);
                af[mf][2] = __float_as_uint(As[r0 * AS_STRIDE + k + tig + 4]);
                af[mf][3] = __float_as_uint(As[(r0 + 8) * AS_STRIDE + k + tig + 4]);
            }
#pragma unroll
            for (int nf = 0; nf < 8; nf++) {
                const int n = nbase + nf * 8 + gid;
                bf[nf][0] = __float_as_uint(Bs[(k + tig) * BS_STRIDE + n]);
                bf[nf][1] = __float_as_uint(Bs[(k + tig + 4) * BS_STRIDE + n]);
            }
#pragma unroll
            for (int mf = 0; mf < 4; mf++)
#pragma unroll
                for (int nf = 0; nf < 8; nf++) {
                    asm volatile(
                        "mma.sync.aligned.m16n8k8.row.col.f32.tf32.tf32.f32 "
                        "{%0,%1,%2,%3}, {%4,%5,%6,%7}, {%8,%9}, {%0,%1,%2,%3};"
                        : "+f"(acc[mf][nf][0]), "+f"(acc[mf][nf][1]),
                          "+f"(acc[mf][nf][2]), "+f"(acc[mf][nf][3])
                        : "r"(af[mf][0]), "r"(af[mf][1]), "r"(af[mf][2]), "r"(af[mf][3]),
                          "r"(bf[nf][0]), "r"(bf[nf][1]));
                }
        }
        __syncthreads();
    }

    // ---- epilogue ----
#pragma unroll
    for (int mf = 0; mf < 4; mf++) {
        const int rr = m0 + mbase + mf * 16 + gid;
#pragma unroll
        for (int nf = 0; nf < 8; nf++) {
            const int cc = n0 + nbase + nf * 8 + 2 * tig;
            const float b0 = bias[cc], b1 = bias[cc + 1];
            size_t o0 = (size_t)rr * N + cc;
            size_t o1 = (size_t)(rr + 8) * N + cc;
            float2 v0, v1;
            v0.x = acc[mf][nf][0] + b0; v0.y = acc[mf][nf][1] + b1;
            v1.x = acc[mf][nf][2] + b0; v1.y = acc[mf][nf][3] + b1;
            if (RES) {
                float2 r0 = *(const float2*)(R + o0);
                float2 r1 = *(const float2*)(R + o1);
                v0.x += r0.x; v0.y += r0.y;
                v1.x += r1.x; v1.y += r1.y;
            }
            *(float2*)(C + o0) = v0;
            *(float2*)(C + o1) = v1;
        }
    }
}

// ============================ flash attention (fp32, unchanged) ============================
#define KSTRIDE 68

__global__ __launch_bounds__(128) void attn_kernel()
{
    __shared__ float ks[64 * KSTRIDE];
    __shared__ float vs[64 * KSTRIDE];
    __shared__ unsigned char pms[64];

    const int qb  = (int)gridDim.x - 1 - (int)blockIdx.x;
    const int h   = blockIdx.y;
    const int b   = blockIdx.z;
    const int tid = threadIdx.x;
    const int q   = qb * 128 + tid;

    float qv[64];
    {
        const float* qrow = g_qkv + (size_t)(b * SS + q) * N3 + h * DD;
#pragma unroll
        for (int d4 = 0; d4 < 16; d4++) {
            float4 v = *(const float4*)(qrow + d4 * 4);
            qv[4 * d4 + 0] = v.x; qv[4 * d4 + 1] = v.y;
            qv[4 * d4 + 2] = v.z; qv[4 * d4 + 3] = v.w;
        }
    }

    float ov[64];
#pragma unroll
    for (int d = 0; d < 64; d++) ov[d] = 0.f;
    float m = -INFINITY, l = 0.f;

    const int warp_qmax = qb * 128 + ((tid >> 5) << 5) + 31;
    const int ntiles = 2 * qb + 2;
    const float* kbase = g_qkv + (size_t)(b * SS) * N3 + FFDIM + h * DD;
    const float* vbase = g_qkv + (size_t)(b * SS) * N3 + 2 * FFDIM + h * DD;

    for (int kt = 0; kt < ntiles; kt++) {
        __syncthreads();
#pragma unroll
        for (int it = 0; it < 8; it++) {
            int idx = it * 128 + tid;
            int row = idx >> 4;
            int c4  = idx & 15;
            size_t g = (size_t)(kt * 64 + row) * N3 + c4 * 4;
            *(float4*)&ks[row * KSTRIDE + c4 * 4] = *(const float4*)(kbase + g);
            *(float4*)&vs[row * KSTRIDE + c4 * 4] = *(const float4*)(vbase + g);
        }
        if (tid < 64) pms[tid] = g_mask[b * SS + kt * 64 + tid];
        __syncthreads();

        if (kt * 64 > warp_qmax) continue;

        for (int j = 0; j < 64; j++) {
            if (pms[j]) continue;
            const int kg = kt * 64 + j;

            float s0 = 0.f, s1 = 0.f, s2 = 0.f, s3 = 0.f;
            const float* kr = &ks[j * KSTRIDE];
#pragma unroll
            for (int d4 = 0; d4 < 16; d4++) {
                float4 kk = *(const float4*)(kr + d4 * 4);
                s0 += qv[4 * d4 + 0] * kk.x;
                s1 += qv[4 * d4 + 1] * kk.y;
                s2 += qv[4 * d4 + 2] * kk.z;
                s3 += qv[4 * d4 + 3] * kk.w;
            }
            float s = (s0 + s1 + s2 + s3) * 0.125f;

            float p = 0.f;
            if (kg <= q) {
                if (s > m) {
                    float c = __expf(m - s);
                    l *= c;
#pragma unroll
                    for (int d = 0; d < 64; d++) ov[d] *= c;
                    m = s;
                    p = 1.f;
                } else {
                    p = __expf(s - m);
                }
                l += p;
            }
            if (__all_sync(0xffffffffu, p == 0.f)) continue;

            const float* vr = &vs[j * KSTRIDE];
#pragma unroll
            for (int d4 = 0; d4 < 16; d4++) {
                float4 vv = *(const float4*)(vr + d4 * 4);
                ov[4 * d4 + 0] += p * vv.x;
                ov[4 * d4 + 1] += p * vv.y;
                ov[4 * d4 + 2] += p * vv.z;
                ov[4 * d4 + 3] += p * vv.w;
            }
        }
    }

    const float inv = (l > 0.f) ? (1.f / l) : 0.f;
    float* orow = g_attn + (size_t)(b * SS + q) * FFDIM + h * DD;
#pragma unroll
    for (int d4 = 0; d4 < 16; d4++) {
        float4 o;
        o.x = ov[4 * d4 + 0] * inv; o.y = ov[4 * d4 + 1] * inv;
        o.z = ov[4 * d4 + 2] * inv; o.w = ov[4 * d4 + 3] * inv;
        *(float4*)(orow + d4 * 4) = o;
    }
}

// ============================ launch ============================
extern "C" void kernel_launch(void* const* d_in, const int* in_sizes, int n_in,
                              void* d_out, int out_size)
{
    const float*         x      = (const float*)d_in[0];
    const unsigned char* pmask  = (const unsigned char*)d_in[1];
    const float*         w_qkv  = (const float*)d_in[2];
    const float*         b_qkv  = (const float*)d_in[3];
    const float*         w_out  = (const float*)d_in[4];
    const float*         b_out  = (const float*)d_in[5];
    float*               out    = (float*)d_out;

    float* qkv = nullptr;
    float* attn = nullptr;
    cudaGetSymbolAddress((void**)&qkv,  g_qkv);
    cudaGetSymbolAddress((void**)&attn, g_attn);

    cudaFuncSetAttribute(tf32_mma_gemm<false>,
                         cudaFuncAttributeMaxDynamicSharedMemorySize, GEMM_SMEM);
    cudaFuncSetAttribute(tf32_mma_gemm<true>,
                         cudaFuncAttributeMaxDynamicSharedMemorySize, GEMM_SMEM);

    mask_canon_kernel<<<1, 256>>>(pmask);

    // GEMM1: [4096,1024] @ [1024,3072] + b_qkv -> g_qkv
    {
        dim3 grid(N3 / 128, MROWS / 128);
        tf32_mma_gemm<false><<<grid, 128, GEMM_SMEM>>>(x, w_qkv, b_qkv, nullptr,
                                                       qkv, N3, FFDIM);
    }
    // Attention
    {
        dim3 grid(SS / 128, HH, BB);
        attn_kernel<<<grid, 128>>>();
    }
    // GEMM2: x + [4096,1024] @ [1024,1024] + b_out -> out
    {
        dim3 grid(FFDIM / 128, MROWS / 128);
        tf32_mma_gemm<true><<<grid, 128, GEMM_SMEM>>>(attn, w_out, b_out, x,
                                                      out, FFDIM, FFDIM);
    }
}

// round 7
// speedup vs baseline: 3.8742x; 2.3281x over previous
#include <cuda_runtime.h>
#include <math.h>
#include <cstdint>

// Problem constants
#define BB 2
#define SS 2048
#define FFDIM 1024
#define HH 16
#define DD 64
#define MROWS (BB * SS)      // 4096
#define N3 (3 * FFDIM)       // 3072

// Scratch
__device__ float g_qkv[(size_t)MROWS * N3];     // 48 MB
__device__ float g_attn[(size_t)MROWS * FFDIM]; // 16 MB
__device__ float g_kc[(size_t)MROWS * FFDIM];   // compacted K, 16 MB
__device__ float g_vc[(size_t)MROWS * FFDIM];   // compacted V, 16 MB
__device__ unsigned char g_mask[MROWS];
__device__ int g_orig[MROWS];                    // per-batch compacted->orig index
__device__ int g_cnt[MROWS];                     // cnt[q] = #valid keys <= q

// ============================ helpers ============================
__device__ __forceinline__ uint32_t smem_u32(const void* p) {
    uint32_t a;
    asm("{ .reg .u64 t; cvta.to.shared.u64 t, %1; cvt.u32.u64 %0, t; }" : "=r"(a) : "l"(p));
    return a;
}
__device__ __forceinline__ void cp_async16(uint32_t dst, const void* src) {
    asm volatile("cp.async.cg.shared.global [%0], [%1], 16;" :: "r"(dst), "l"(src));
}
#define CP_COMMIT() asm volatile("cp.async.commit_group;" ::: "memory")
#define CP_WAIT2()  asm volatile("cp.async.wait_group 2;" ::: "memory")

__device__ __forceinline__ float rna_tf32(float v) {
    uint32_t o;
    asm("cvt.rna.tf32.f32 %0, %1;" : "=r"(o) : "f"(v));
    return __uint_as_float(o);
}
__device__ __forceinline__ void mma_tf32(float* c, const uint32_t* a, const uint32_t* b) {
    asm volatile(
        "mma.sync.aligned.m16n8k8.row.col.f32.tf32.tf32.f32 "
        "{%0,%1,%2,%3}, {%4,%5,%6,%7}, {%8,%9}, {%0,%1,%2,%3};"
        : "+f"(c[0]), "+f"(c[1]), "+f"(c[2]), "+f"(c[3])
        : "r"(a[0]), "r"(a[1]), "r"(a[2]), "r"(a[3]), "r"(b[0]), "r"(b[1]));
}

// ============================ mask canonicalization ============================
__global__ void mask_canon_kernel(const unsigned char* __restrict__ raw)
{
    __shared__ unsigned s_flags;
    const unsigned* w = (const unsigned*)raw;
    const int tid = threadIdx.x;
    if (tid == 0) s_flags = 0;
    __syncthreads();
    unsigned flags = 0;
    for (int i = tid; i < 1024; i += 256) {
        unsigned v = w[i];
        if (v > 1u) flags |= 1u;
        if (v != 0u && v != 0x3f800000u) flags |= 2u;
    }
    atomicOr(&s_flags, flags);
    __syncthreads();
    const unsigned f = s_flags;
    if (!(f & 1u)) {
        for (int i = tid; i < MROWS; i += 256) g_mask[i] = (w[i] != 0u) ? 1 : 0;
    } else if (!(f & 2u)) {
        const float* fp = (const float*)raw;
        for (int i = tid; i < MROWS; i += 256) g_mask[i] = (fp[i] != 0.f) ? 1 : 0;
    } else {
        for (int i = tid; i < MROWS; i += 256) g_mask[i] = (raw[i] != 0) ? 1 : 0;
    }
}

// ============================ compaction scan ============================
// One CTA per batch: cnt[q] = inclusive count of valid (unpadded) keys <= q,
// orig[j] = original index of j-th valid key.
__global__ __launch_bounds__(256) void compact_kernel()
{
    __shared__ int part[256];
    const int b = blockIdx.x, tid = threadIdx.x, base = b * SS;
    int loc[8], s = 0;
#pragma unroll
    for (int i = 0; i < 8; i++) {
        int v = g_mask[base + tid * 8 + i] ? 0 : 1;
        loc[i] = v; s += v;
    }
    part[tid] = s;
    __syncthreads();
    for (int off = 1; off < 256; off <<= 1) {
        int v = (tid >= off) ? part[tid - off] : 0;
        __syncthreads();
        part[tid] += v;
        __syncthreads();
    }
    int run = part[tid] - s;
#pragma unroll
    for (int i = 0; i < 8; i++) {
        run += loc[i];
        g_cnt[base + tid * 8 + i] = run;
        if (loc[i]) g_orig[base + run - 1] = tid * 8 + i;
    }
}

// ============================ K/V gather (compacted, tf32-rounded) ============================
__global__ __launch_bounds__(256) void gather_kernel()
{
    const int b = blockIdx.y;
    const int nv = g_cnt[b * SS + SS - 1];
    const int j0 = blockIdx.x * 8;
    const int tid = threadIdx.x;
#pragma unroll
    for (int r = 0; r < 8; r++) {
        const int j = j0 + r;
        if (j >= nv) return;
        const int src = g_orig[b * SS + j];
        const float4* ks = (const float4*)(g_qkv + (size_t)(b * SS + src) * N3 + FFDIM);
        const float4* vs = (const float4*)(g_qkv + (size_t)(b * SS + src) * N3 + 2 * FFDIM);
        float4* kd = (float4*)(g_kc + (size_t)(b * SS + j) * FFDIM);
        float4* vd = (float4*)(g_vc + (size_t)(b * SS + j) * FFDIM);
        float4 k4 = ks[tid];
        k4.x = rna_tf32(k4.x); k4.y = rna_tf32(k4.y);
        k4.z = rna_tf32(k4.z); k4.w = rna_tf32(k4.w);
        kd[tid] = k4;
        float4 v4 = vs[tid];
        v4.x = rna_tf32(v4.x); v4.y = rna_tf32(v4.y);
        v4.z = rna_tf32(v4.z); v4.w = rna_tf32(v4.w);
        vd[tid] = v4;
    }
}

// ============================ tf32 mma.sync GEMM (unchanged from R6) ============================
#define BKC 32
#define STAGES 3
#define AS_STRIDE 36
#define BS_STRIDE 132
#define A_STAGE (128 * AS_STRIDE)
#define B_STAGE (BKC * BS_STRIDE)
#define STAGE_FLOATS (A_STAGE + B_STAGE)
#define GEMM_SMEM (STAGES * STAGE_FLOATS * 4)

template <bool RES>
__global__ __launch_bounds__(128, 2) void tf32_mma_gemm(
    const float* __restrict__ A, const float* __restrict__ W,
    const float* __restrict__ bias, const float* __restrict__ R,
    float* __restrict__ C, int N, int K)
{
    extern __shared__ float sm[];
    const uint32_t smb = smem_u32(sm);
    const int tid  = threadIdx.x;
    const int wid  = tid >> 5;
    const int lane = tid & 31;
    const int gid  = lane >> 2;
    const int tig  = lane & 3;
    const int mbase = (wid & 1) * 64;
    const int nbase = (wid >> 1) * 64;
    const int m0 = blockIdx.y * 128;
    const int n0 = blockIdx.x * 128;

    const int arow = tid >> 3, ac4 = tid & 7;
    const int bkr  = tid >> 5, bc4 = tid & 31;

    const float* Abase = A + (size_t)m0 * K;
    const float* Bbase = W + n0;

    auto issue_stage = [&](int kc, int buf) {
        const float* Asrc = Abase + kc * BKC;
        uint32_t ab = smb + (uint32_t)(buf * STAGE_FLOATS) * 4u;
#pragma unroll
        for (int it = 0; it < 8; it++) {
            int row = arow + it * 16;
            cp_async16(ab + (uint32_t)(row * AS_STRIDE + ac4 * 4) * 4u,
                       Asrc + (size_t)row * K + ac4 * 4);
        }
        const float* Bsrc = Bbase + (size_t)(kc * BKC) * N;
        uint32_t bb = smb + (uint32_t)(buf * STAGE_FLOATS + A_STAGE) * 4u;
#pragma unroll
        for (int it = 0; it < 8; it++) {
            int kr = bkr + it * 4;
            cp_async16(bb + (uint32_t)(kr * BS_STRIDE + bc4 * 4) * 4u,
                       Bsrc + (size_t)kr * N + bc4 * 4);
        }
    };

    float acc[4][8][4];
#pragma unroll
    for (int i = 0; i < 4; i++)
#pragma unroll
        for (int j = 0; j < 8; j++)
#pragma unroll
            for (int c = 0; c < 4; c++) acc[i][j][c] = 0.f;

    const int nch = K / BKC;

    issue_stage(0, 0); CP_COMMIT();
    issue_stage(1, 1); CP_COMMIT();

    for (int ch = 0; ch < nch; ch++) {
        if (ch + 2 < nch) issue_stage(ch + 2, (ch + 2) % STAGES);
        CP_COMMIT();
        CP_WAIT2();
        __syncthreads();

        const float* As = sm + (ch % STAGES) * STAGE_FLOATS;
        const float* Bs = As + A_STAGE;
#pragma unroll
        for (int ks = 0; ks < 4; ks++) {
            const int k = ks * 8;
            uint32_t af[4][4], bf[8][2];
#pragma unroll
            for (int mf = 0; mf < 4; mf++) {
                const int r0 = mbase + mf * 16 + gid;
                af[mf][0] = __float_as_uint(As[r0 * AS_STRIDE + k + tig]);
                af[mf][1] = __float_as_uint(As[(r0 + 8) * AS_STRIDE + k + tig]);
                af[mf][2] = __float_as_uint(As[r0 * AS_STRIDE + k + tig + 4]);
                af[mf][3] = __float_as_uint(As[(r0 + 8) * AS_STRIDE + k + tig + 4]);
            }
#pragma unroll
            for (int nf = 0; nf < 8; nf++) {
                const int n = nbase + nf * 8 + gid;
                bf[nf][0] = __float_as_uint(Bs[(k + tig) * BS_STRIDE + n]);
                bf[nf][1] = __float_as_uint(Bs[(k + tig + 4) * BS_STRIDE + n]);
            }
#pragma unroll
            for (int mf = 0; mf < 4; mf++)
#pragma unroll
                for (int nf = 0; nf < 8; nf++)
                    mma_tf32(acc[mf][nf], af[mf], bf[nf]);
        }
        __syncthreads();
    }

#pragma unroll
    for (int mf = 0; mf < 4; mf++) {
        const int rr = m0 + mbase + mf * 16 + gid;
#pragma unroll
        for (int nf = 0; nf < 8; nf++) {
            const int cc = n0 + nbase + nf * 8 + 2 * tig;
            const float b0 = bias[cc], b1 = bias[cc + 1];
            size_t o0 = (size_t)rr * N + cc;
            size_t o1 = (size_t)(rr + 8) * N + cc;
            float2 v0, v1;
            v0.x = acc[mf][nf][0] + b0; v0.y = acc[mf][nf][1] + b1;
            v1.x = acc[mf][nf][2] + b0; v1.y = acc[mf][nf][3] + b1;
            if (RES) {
                float2 r0 = *(const float2*)(R + o0);
                float2 r1 = *(const float2*)(R + o1);
                v0.x += r0.x; v0.y += r0.y;
                v1.x += r1.x; v1.y += r1.y;
            }
            *(float2*)(C + o0) = v0;
            *(float2*)(C + o1) = v1;
        }
    }
}

// ============================ flash attention via mma.sync tf32 ============================
// Grid (S/64, H, B), 128 threads = 4 warps x 16 q-rows. Compacted keys: valid
// keys for row q are exactly the first cnt[q] compacted entries (prefix).
#define QSTR 68
#define KSTR 68
#define VSTR 72
#define ATTN_Q 0
#define ATTN_K (64 * QSTR)                     // 4352
#define ATTN_V (ATTN_K + 64 * KSTR)           // 8704
#define ATTN_P (ATTN_V + 64 * VSTR)           // 13312
#define ATTN_SMEM ((ATTN_P + 64 * QSTR) * 4)  // 70656 bytes

__global__ __launch_bounds__(128) void attn_mma_kernel()
{
    extern __shared__ float sm[];
    float* Qs = sm + ATTN_Q;
    float* Ks = sm + ATTN_K;
    float* Vs = sm + ATTN_V;
    float* Ps = sm + ATTN_P;

    const int qb  = (int)gridDim.x - 1 - (int)blockIdx.x;
    const int h   = blockIdx.y;
    const int b   = blockIdx.z;
    const int tid = threadIdx.x;
    const int w   = tid >> 5;
    const int lane = tid & 31;
    const int gid = lane >> 2;
    const int tig = lane & 3;
    const int q0 = qb * 64;

    // Stage Q (pre-scaled by 1/sqrt(D), tf32-rounded)
#pragma unroll
    for (int it = 0; it < 8; it++) {
        int idx = it * 128 + tid;
        int row = idx >> 4, c4 = idx & 15;
        float4 v = *(const float4*)(g_qkv + (size_t)(b * SS + q0 + row) * N3 + h * DD + c4 * 4);
        v.x = rna_tf32(v.x * 0.125f); v.y = rna_tf32(v.y * 0.125f);
        v.z = rna_tf32(v.z * 0.125f); v.w = rna_tf32(v.w * 0.125f);
        *(float4*)&Qs[row * QSTR + c4 * 4] = v;
    }
    __syncthreads();

    // Per-warp Q fragments (rows w*16+gid, +8)
    const int r0 = w * 16 + gid;
    uint32_t aq[8][4];
#pragma unroll
    for (int ks = 0; ks < 8; ks++) {
        aq[ks][0] = __float_as_uint(Qs[r0 * QSTR + ks * 8 + tig]);
        aq[ks][1] = __float_as_uint(Qs[(r0 + 8) * QSTR + ks * 8 + tig]);
        aq[ks][2] = __float_as_uint(Qs[r0 * QSTR + ks * 8 + tig + 4]);
        aq[ks][3] = __float_as_uint(Qs[(r0 + 8) * QSTR + ks * 8 + tig + 4]);
    }

    const int cnt_r0   = g_cnt[b * SS + q0 + w * 16 + gid];
    const int cnt_r1   = g_cnt[b * SS + q0 + w * 16 + gid + 8];
    const int warp_cnt = g_cnt[b * SS + q0 + w * 16 + 15];
    const int nkeys    = g_cnt[b * SS + q0 + 63];
    const int ntiles   = (nkeys + 63) >> 6;

    float m0 = -1e30f, m1 = -1e30f, l0 = 0.f, l1 = 0.f;
    float co[8][4];
#pragma unroll
    for (int nt = 0; nt < 8; nt++)
#pragma unroll
        for (int i = 0; i < 4; i++) co[nt][i] = 0.f;

    for (int kt = 0; kt < ntiles; kt++) {
        __syncthreads();
#pragma unroll
        for (int it = 0; it < 8; it++) {
            int idx = it * 128 + tid;
            int row = idx >> 4, c4 = idx & 15;
            size_t g = (size_t)(b * SS + kt * 64 + row) * FFDIM + h * DD + c4 * 4;
            *(float4*)&Ks[row * KSTR + c4 * 4] = *(const float4*)(g_kc + g);
            *(float4*)&Vs[row * VSTR + c4 * 4] = *(const float4*)(g_vc + g);
        }
        __syncthreads();

        if (kt * 64 >= warp_cnt) continue;   // this warp's rows see no keys here

        // S = Q @ K^T
        float c[8][4];
#pragma unroll
        for (int nt = 0; nt < 8; nt++)
#pragma unroll
            for (int i = 0; i < 4; i++) c[nt][i] = 0.f;
#pragma unroll
        for (int ks = 0; ks < 8; ks++) {
            uint32_t bf[8][2];
#pragma unroll
            for (int nt = 0; nt < 8; nt++) {
                bf[nt][0] = __float_as_uint(Ks[(nt * 8 + gid) * KSTR + ks * 8 + tig]);
                bf[nt][1] = __float_as_uint(Ks[(nt * 8 + gid) * KSTR + ks * 8 + tig + 4]);
            }
#pragma unroll
            for (int nt = 0; nt < 8; nt++)
                mma_tf32(c[nt], aq[ks], bf[nt]);
        }

        // Prefix-boundary mask + tile row max
        float t0 = -1e30f, t1 = -1e30f;
#pragma unroll
        for (int nt = 0; nt < 8; nt++) {
            const int jc = kt * 64 + nt * 8 + 2 * tig;
            c[nt][0] = (jc     < cnt_r0) ? c[nt][0] : -1e30f;
            c[nt][1] = (jc + 1 < cnt_r0) ? c[nt][1] : -1e30f;
            c[nt][2] = (jc     < cnt_r1) ? c[nt][2] : -1e30f;
            c[nt][3] = (jc + 1 < cnt_r1) ? c[nt][3] : -1e30f;
            t0 = fmaxf(t0, fmaxf(c[nt][0], c[nt][1]));
            t1 = fmaxf(t1, fmaxf(c[nt][2], c[nt][3]));
        }
        t0 = fmaxf(t0, __shfl_xor_sync(0xffffffffu, t0, 1));
        t0 = fmaxf(t0, __shfl_xor_sync(0xffffffffu, t0, 2));
        t1 = fmaxf(t1, __shfl_xor_sync(0xffffffffu, t1, 1));
        t1 = fmaxf(t1, __shfl_xor_sync(0xffffffffu, t1, 2));

        const float mn0 = fmaxf(m0, t0), mn1 = fmaxf(m1, t1);
        const float al0 = __expf(m0 - mn0), al1 = __expf(m1 - mn1);
        m0 = mn0; m1 = mn1;

        float rs0 = 0.f, rs1 = 0.f;
#pragma unroll
        for (int nt = 0; nt < 8; nt++) {
            float p0 = rna_tf32(__expf(c[nt][0] - mn0));
            float p1 = rna_tf32(__expf(c[nt][1] - mn0));
            float p2 = rna_tf32(__expf(c[nt][2] - mn1));
            float p3 = rna_tf32(__expf(c[nt][3] - mn1));
            c[nt][0] = p0; c[nt][1] = p1; c[nt][2] = p2; c[nt][3] = p3;
            rs0 += p0 + p1; rs1 += p2 + p3;
        }
        rs0 += __shfl_xor_sync(0xffffffffu, rs0, 1);
        rs0 += __shfl_xor_sync(0xffffffffu, rs0, 2);
        rs1 += __shfl_xor_sync(0xffffffffu, rs1, 1);
        rs1 += __shfl_xor_sync(0xffffffffu, rs1, 2);
        l0 = l0 * al0 + rs0;
        l1 = l1 * al1 + rs1;

#pragma unroll
        for (int nt = 0; nt < 8; nt++) {
            co[nt][0] *= al0; co[nt][1] *= al0;
            co[nt][2] *= al1; co[nt][3] *= al1;
        }

        // P -> per-warp-private smem rows, then PV mma
#pragma unroll
        for (int nt = 0; nt < 8; nt++) {
            Ps[r0 * QSTR + nt * 8 + 2 * tig]           = c[nt][0];
            Ps[r0 * QSTR + nt * 8 + 2 * tig + 1]       = c[nt][1];
            Ps[(r0 + 8) * QSTR + nt * 8 + 2 * tig]     = c[nt][2];
            Ps[(r0 + 8) * QSTR + nt * 8 + 2 * tig + 1] = c[nt][3];
        }
        __syncwarp();
#pragma unroll
        for (int ks = 0; ks < 8; ks++) {
            uint32_t ap[4], bf[8][2];
            ap[0] = __float_as_uint(Ps[r0 * QSTR + ks * 8 + tig]);
            ap[1] = __float_as_uint(Ps[(r0 + 8) * QSTR + ks * 8 + tig]);
            ap[2] = __float_as_uint(Ps[r0 * QSTR + ks * 8 + tig + 4]);
            ap[3] = __float_as_uint(Ps[(r0 + 8) * QSTR + ks * 8 + tig + 4]);
#pragma unroll
            for (int nt = 0; nt < 8; nt++) {
                bf[nt][0] = __float_as_uint(Vs[(ks * 8 + tig) * VSTR + nt * 8 + gid]);
                bf[nt][1] = __float_as_uint(Vs[(ks * 8 + tig + 4) * VSTR + nt * 8 + gid]);
            }
#pragma unroll
            for (int nt = 0; nt < 8; nt++)
                mma_tf32(co[nt], ap, bf[nt]);
        }
        __syncwarp();
    }

    // Epilogue: normalize, zero fully-masked rows
    const float inv0 = (cnt_r0 > 0) ? (1.f / l0) : 0.f;
    const float inv1 = (cnt_r1 > 0) ? (1.f / l1) : 0.f;
    float* o0 = g_attn + (size_t)(b * SS + q0 + r0) * FFDIM + h * DD;
    float* o1 = g_attn + (size_t)(b * SS + q0 + r0 + 8) * FFDIM + h * DD;
#pragma unroll
    for (int nt = 0; nt < 8; nt++) {
        float2 u0, u1;
        u0.x = co[nt][0] * inv0; u0.y = co[nt][1] * inv0;
        u1.x = co[nt][2] * inv1; u1.y = co[nt][3] * inv1;
        *(float2*)(o0 + nt * 8 + 2 * tig) = u0;
        *(float2*)(o1 + nt * 8 + 2 * tig) = u1;
    }
}

// ============================ launch ============================
extern "C" void kernel_launch(void* const* d_in, const int* in_sizes, int n_in,
                              void* d_out, int out_size)
{
    const float*         x      = (const float*)d_in[0];
    const unsigned char* pmask  = (const unsigned char*)d_in[1];
    const float*         w_qkv  = (const float*)d_in[2];
    const float*         b_qkv  = (const float*)d_in[3];
    const float*         w_out  = (const float*)d_in[4];
    const float*         b_out  = (const float*)d_in[5];
    float*               out    = (float*)d_out;

    float* qkv = nullptr;
    float* attn = nullptr;
    cudaGetSymbolAddress((void**)&qkv,  g_qkv);
    cudaGetSymbolAddress((void**)&attn, g_attn);

    cudaFuncSetAttribute(tf32_mma_gemm<false>,
                         cudaFuncAttributeMaxDynamicSharedMemorySize, GEMM_SMEM);
    cudaFuncSetAttribute(tf32_mma_gemm<true>,
                         cudaFuncAttributeMaxDynamicSharedMemorySize, GEMM_SMEM);
    cudaFuncSetAttribute(attn_mma_kernel,
                         cudaFuncAttributeMaxDynamicSharedMemorySize, ATTN_SMEM);

    mask_canon_kernel<<<1, 256>>>(pmask);
    compact_kernel<<<BB, 256>>>();

    // GEMM1: [4096,1024] @ [1024,3072] + b_qkv -> g_qkv
    {
        dim3 grid(N3 / 128, MROWS / 128);
        tf32_mma_gemm<false><<<grid, 128, GEMM_SMEM>>>(x, w_qkv, b_qkv, nullptr,
                                                       qkv, N3, FFDIM);
    }
    // Gather compacted K/V (needs GEMM1 output)
    {
        dim3 grid(SS / 8, BB);
        gather_kernel<<<grid, 256>>>();
    }
    // Attention
    {
        dim3 grid(SS / 64, HH, BB);
        attn_mma_kernel<<<grid, 128, ATTN_SMEM>>>();
    }
    // GEMM2: x + [4096,1024] @ [1024,1024] + b_out -> out
    {
        dim3 grid(FFDIM / 128, MROWS / 128);
        tf32_mma_gemm<true><<<grid, 128, GEMM_SMEM>>>(attn, w_out, b_out, x,
                                                      out, FFDIM, FFDIM);
    }
}

// round 9
// speedup vs baseline: 4.7966x; 1.2381x over previous
#include <cuda_runtime.h>
#include <math.h>
#include <cstdint>

// Problem constants
#define BB 2
#define SS 2048
#define FFDIM 1024
#define HH 16
#define DD 64
#define MROWS (BB * SS)      // 4096
#define N3 (3 * FFDIM)       // 3072

// Scratch
__device__ float g_q[(size_t)MROWS * FFDIM];    // Q projection, 16 MB
__device__ float g_attn[(size_t)MROWS * FFDIM]; // attention output, 16 MB
__device__ float g_kc[(size_t)MROWS * FFDIM];   // compacted K (tf32-rounded), 16 MB
__device__ float g_vc[(size_t)MROWS * FFDIM];   // compacted V (tf32-rounded), 16 MB
__device__ unsigned char g_mask[MROWS];
__device__ int g_orig[MROWS];                    // per-batch compacted->orig index
__device__ int g_cnt[MROWS];                     // cnt[q] = #valid keys <= q

// ============================ helpers ============================
__device__ __forceinline__ uint32_t smem_u32(const void* p) {
    uint32_t a;
    asm("{ .reg .u64 t; cvta.to.shared.u64 t, %1; cvt.u32.u64 %0, t; }" : "=r"(a) : "l"(p));
    return a;
}
__device__ __forceinline__ void cp_async16(uint32_t dst, const void* src) {
    asm volatile("cp.async.cg.shared.global [%0], [%1], 16;" :: "r"(dst), "l"(src));
}
#define CP_COMMIT() asm volatile("cp.async.commit_group;" ::: "memory")
#define CP_WAIT2()  asm volatile("cp.async.wait_group 2;" ::: "memory")

__device__ __forceinline__ float rna_tf32(float v) {
    uint32_t o;
    asm("cvt.rna.tf32.f32 %0, %1;" : "=r"(o) : "f"(v));
    return __uint_as_float(o);
}
__device__ __forceinline__ void mma_tf32(float* c, const uint32_t* a, const uint32_t* b) {
    asm volatile(
        "mma.sync.aligned.m16n8k8.row.col.f32.tf32.tf32.f32 "
        "{%0,%1,%2,%3}, {%4,%5,%6,%7}, {%8,%9}, {%0,%1,%2,%3};"
        : "+f"(c[0]), "+f"(c[1]), "+f"(c[2]), "+f"(c[3])
        : "r"(a[0]), "r"(a[1]), "r"(a[2]), "r"(a[3]), "r"(b[0]), "r"(b[1]));
}

// ============================ mask canonicalization ============================
__global__ void mask_canon_kernel(const unsigned char* __restrict__ raw)
{
    __shared__ unsigned s_flags;
    const unsigned* w = (const unsigned*)raw;
    const int tid = threadIdx.x;
    if (tid == 0) s_flags = 0;
    __syncthreads();
    unsigned flags = 0;
    for (int i = tid; i < 1024; i += 256) {
        unsigned v = w[i];
        if (v > 1u) flags |= 1u;
        if (v != 0u && v != 0x3f800000u) flags |= 2u;
    }
    atomicOr(&s_flags, flags);
    __syncthreads();
    const unsigned f = s_flags;
    if (!(f & 1u)) {
        for (int i = tid; i < MROWS; i += 256) g_mask[i] = (w[i] != 0u) ? 1 : 0;
    } else if (!(f & 2u)) {
        const float* fp = (const float*)raw;
        for (int i = tid; i < MROWS; i += 256) g_mask[i] = (fp[i] != 0.f) ? 1 : 0;
    } else {
        for (int i = tid; i < MROWS; i += 256) g_mask[i] = (raw[i] != 0) ? 1 : 0;
    }
}

// ============================ compaction scan ============================
__global__ __launch_bounds__(256) void compact_kernel()
{
    __shared__ int part[256];
    const int b = blockIdx.x, tid = threadIdx.x, base = b * SS;
    int loc[8], s = 0;
#pragma unroll
    for (int i = 0; i < 8; i++) {
        int v = g_mask[base + tid * 8 + i] ? 0 : 1;
        loc[i] = v; s += v;
    }
    part[tid] = s;
    __syncthreads();
    for (int off = 1; off < 256; off <<= 1) {
        int v = (tid >= off) ? part[tid - off] : 0;
        __syncthreads();
        part[tid] += v;
        __syncthreads();
    }
    int run = part[tid] - s;
#pragma unroll
    for (int i = 0; i < 8; i++) {
        run += loc[i];
        g_cnt[base + tid * 8 + i] = run;
        if (loc[i]) g_orig[base + run - 1] = tid * 8 + i;
    }
}

// ============================ tf32 mma.sync GEMM ============================
// MODE 0: C[M,N] = A@W + bias              (Q projection / generic)
// MODE 1: C[M,N] = A@W + bias + R          (output projection + residual)
// MODE 2: KV projection on COMPACTED rows: A rows gathered via g_orig,
//         output split to g_kc/g_vc with tf32 rounding; CTA early-exit
//         when its whole m-tile is beyond the batch's valid count.
// 128 threads = 4 warps (2m x 2n), block tile 128x128, BK=32, cp.async x3.
#define BKC 32
#define STAGES 3
#define AS_STRIDE 36
#define BS_STRIDE 132
#define A_STAGE (128 * AS_STRIDE)
#define B_STAGE (BKC * BS_STRIDE)
#define STAGE_FLOATS (A_STAGE + B_STAGE)
#define GEMM_SMEM (STAGES * STAGE_FLOATS * 4)

template <int MODE>
__global__ __launch_bounds__(128, 2) void tf32_mma_gemm(
    const float* __restrict__ A, const float* __restrict__ W,
    const float* __restrict__ bias, const float* __restrict__ R,
    float* __restrict__ C, int N, int ldw, int K)
{
    extern __shared__ float sm[];
    __shared__ int rowidx[128];
    const uint32_t smb = smem_u32(sm);
    const int tid  = threadIdx.x;
    const int wid  = tid >> 5;
    const int lane = tid & 31;
    const int gid  = lane >> 2;
    const int tig  = lane & 3;
    const int mbase = (wid & 1) * 64;
    const int nbase = (wid >> 1) * 64;
    const int m0 = blockIdx.y * 128;
    const int n0 = blockIdx.x * 128;

    int bb = 0, m0loc = m0;
    if (MODE == 2) {
        bb = m0 / SS;
        m0loc = m0 - bb * SS;
        const int nv = g_cnt[bb * SS + SS - 1];
        if (m0loc >= nv) return;                   // whole tile beyond valid keys
        if (tid < 128) {
            int j = m0loc + tid;
            rowidx[tid] = (j < nv) ? g_orig[bb * SS + j] : 0;
        }
        __syncthreads();
    }

    const int arow = tid >> 3, ac4 = tid & 7;
    const int bkr  = tid >> 5, bc4 = tid & 31;

    const float* Abase = A + (size_t)m0 * K;       // MODE 0/1 only
    const float* Bbase = W + n0;

    auto issue_stage = [&](int kc, int buf) {
        uint32_t ab = smb + (uint32_t)(buf * STAGE_FLOATS) * 4u;
#pragma unroll
        for (int it = 0; it < 8; it++) {
            int row = arow + it * 16;
            const float* src;
            if (MODE == 2)
                src = A + (size_t)(bb * SS + rowidx[row]) * K + kc * BKC + ac4 * 4;
            else
                src = Abase + (size_t)row * K + kc * BKC + ac4 * 4;
            cp_async16(ab + (uint32_t)(row * AS_STRIDE + ac4 * 4) * 4u, src);
        }
        const float* Bsrc = Bbase + (size_t)(kc * BKC) * ldw;
        uint32_t bbuf = smb + (uint32_t)(buf * STAGE_FLOATS + A_STAGE) * 4u;
#pragma unroll
        for (int it = 0; it < 8; it++) {
            int kr = bkr + it * 4;
            cp_async16(bbuf + (uint32_t)(kr * BS_STRIDE + bc4 * 4) * 4u,
                       Bsrc + (size_t)kr * ldw + bc4 * 4);
        }
    };

    float acc[4][8][4];
#pragma unroll
    for (int i = 0; i < 4; i++)
#pragma unroll
        for (int j = 0; j < 8; j++)
#pragma unroll
            for (int c = 0; c < 4; c++) acc[i][j][c] = 0.f;

    const int nch = K / BKC;

    issue_stage(0, 0); CP_COMMIT();
    issue_stage(1, 1); CP_COMMIT();

    for (int ch = 0; ch < nch; ch++) {
        if (ch + 2 < nch) issue_stage(ch + 2, (ch + 2) % STAGES);
        CP_COMMIT();
        CP_WAIT2();
        __syncthreads();

        const float* As = sm + (ch % STAGES) * STAGE_FLOATS;
        const float* Bs = As + A_STAGE;
#pragma unroll
        for (int ks = 0; ks < 4; ks++) {
            const int k = ks * 8;
            uint32_t af[4][4], bf[8][2];
#pragma unroll
            for (int mf = 0; mf < 4; mf++) {
                const int r0 = mbase + mf * 16 + gid;
                af[mf][0] = __float_as_uint(As[r0 * AS_STRIDE + k + tig]);
                af[mf][1] = __float_as_uint(As[(r0 + 8) * AS_STRIDE + k + tig]);
                af[mf][2] = __float_as_uint(As[r0 * AS_STRIDE + k + tig + 4]);
                af[mf][3] = __float_as_uint(As[(r0 + 8) * AS_STRIDE + k + tig + 4]);
            }
#pragma unroll
            for (int nf = 0; nf < 8; nf++) {
                const int n = nbase + nf * 8 + gid;
                bf[nf][0] = __float_as_uint(Bs[(k + tig) * BS_STRIDE + n]);
                bf[nf][1] = __float_as_uint(Bs[(k + tig + 4) * BS_STRIDE + n]);
            }
#pragma unroll
            for (int mf = 0; mf < 4; mf++)
#pragma unroll
                for (int nf = 0; nf < 8; nf++)
                    mma_tf32(acc[mf][nf], af[mf], bf[nf]);
        }
        __syncthreads();
    }

    // ---- epilogue ----
    if (MODE == 2) {
        // split output: cols [0,1024) -> g_kc, [1024,2048) -> g_vc; rna rounding
        float* Cb = (n0 < FFDIM) ? (g_kc + n0) : (g_vc + (n0 - FFDIM));
#pragma unroll
        for (int mf = 0; mf < 4; mf++) {
            const int m = m0loc + mbase + mf * 16 + gid;
            const size_t r0o = (size_t)(bb * SS + m) * FFDIM;
            const size_t r1o = (size_t)(bb * SS + m + 8) * FFDIM;
#pragma unroll
            for (int nf = 0; nf < 8; nf++) {
                const int cl = nbase + nf * 8 + 2 * tig;
                const float b0 = bias[n0 + cl], b1 = bias[n0 + cl + 1];
                float2 v0, v1;
                v0.x = rna_tf32(acc[mf][nf][0] + b0);
                v0.y = rna_tf32(acc[mf][nf][1] + b1);
                v1.x = rna_tf32(acc[mf][nf][2] + b0);
                v1.y = rna_tf32(acc[mf][nf][3] + b1);
                *(float2*)(Cb + r0o + cl) = v0;
                *(float2*)(Cb + r1o + cl) = v1;
            }
        }
    } else {
#pragma unroll
        for (int mf = 0; mf < 4; mf++) {
            const int rr = m0 + mbase + mf * 16 + gid;
#pragma unroll
            for (int nf = 0; nf < 8; nf++) {
                const int cc = n0 + nbase + nf * 8 + 2 * tig;
                const float b0 = bias[cc], b1 = bias[cc + 1];
                size_t o0 = (size_t)rr * N + cc;
                size_t o1 = (size_t)(rr + 8) * N + cc;
                float2 v0, v1;
                v0.x = acc[mf][nf][0] + b0; v0.y = acc[mf][nf][1] + b1;
                v1.x = acc[mf][nf][2] + b0; v1.y = acc[mf][nf][3] + b1;
                if (MODE == 1) {
                    float2 r0 = *(const float2*)(R + o0);
                    float2 r1 = *(const float2*)(R + o1);
                    v0.x += r0.x; v0.y += r0.y;
                    v1.x += r1.x; v1.y += r1.y;
                }
                *(float2*)(C + o0) = v0;
                *(float2*)(C + o1) = v1;
            }
        }
    }
}

// ============================ flash attention via mma.sync tf32 ============================
#define QSTR 68
#define KSTR 68
#define VSTR 72
#define ATTN_Q 0
#define ATTN_K (64 * QSTR)
#define ATTN_V (ATTN_K + 64 * KSTR)
#define ATTN_P (ATTN_V + 64 * VSTR)
#define ATTN_SMEM ((ATTN_P + 64 * QSTR) * 4)

__global__ __launch_bounds__(128) void attn_mma_kernel()
{
    extern __shared__ float sm[];
    float* Qs = sm + ATTN_Q;
    float* Ks = sm + ATTN_K;
    float* Vs = sm + ATTN_V;
    float* Ps = sm + ATTN_P;

    const int qb  = (int)gridDim.x - 1 - (int)blockIdx.x;
    const int h   = blockIdx.y;
    const int b   = blockIdx.z;
    const int tid = threadIdx.x;
    const int w   = tid >> 5;
    const int lane = tid & 31;
    const int gid = lane >> 2;
    const int tig = lane & 3;
    const int q0 = qb * 64;

    // Stage Q from g_q (pre-scaled by 1/sqrt(D), tf32-rounded)
#pragma unroll
    for (int it = 0; it < 8; it++) {
        int idx = it * 128 + tid;
        int row = idx >> 4, c4 = idx & 15;
        float4 v = *(const float4*)(g_q + (size_t)(b * SS + q0 + row) * FFDIM + h * DD + c4 * 4);
        v.x = rna_tf32(v.x * 0.125f); v.y = rna_tf32(v.y * 0.125f);
        v.z = rna_tf32(v.z * 0.125f); v.w = rna_tf32(v.w * 0.125f);
        *(float4*)&Qs[row * QSTR + c4 * 4] = v;
    }
    __syncthreads();

    const int r0 = w * 16 + gid;
    uint32_t aq[8][4];
#pragma unroll
    for (int ks = 0; ks < 8; ks++) {
        aq[ks][0] = __float_as_uint(Qs[r0 * QSTR + ks * 8 + tig]);
        aq[ks][1] = __float_as_uint(Qs[(r0 + 8) * QSTR + ks * 8 + tig]);
        aq[ks][2] = __float_as_uint(Qs[r0 * QSTR + ks * 8 + tig + 4]);
        aq[ks][3] = __float_as_uint(Qs[(r0 + 8) * QSTR + ks * 8 + tig + 4]);
    }

    const int cnt_r0   = g_cnt[b * SS + q0 + w * 16 + gid];
    const int cnt_r1   = g_cnt[b * SS + q0 + w * 16 + gid + 8];
    const int warp_cnt = g_cnt[b * SS + q0 + w * 16 + 15];
    const int nkeys    = g_cnt[b * SS + q0 + 63];
    const int ntiles   = (nkeys + 63) >> 6;

    float m0 = -1e30f, m1 = -1e30f, l0 = 0.f, l1 = 0.f;
    float co[8][4];
#pragma unroll
    for (int nt = 0; nt < 8; nt++)
#pragma unroll
        for (int i = 0; i < 4; i++) co[nt][i] = 0.f;

    for (int kt = 0; kt < ntiles; kt++) {
        __syncthreads();
#pragma unroll
        for (int it = 0; it < 8; it++) {
            int idx = it * 128 + tid;
            int row = idx >> 4, c4 = idx & 15;
            size_t g = (size_t)(b * SS + kt * 64 + row) * FFDIM + h * DD + c4 * 4;
            *(float4*)&Ks[row * KSTR + c4 * 4] = *(const float4*)(g_kc + g);
            *(float4*)&Vs[row * VSTR + c4 * 4] = *(const float4*)(g_vc + g);
        }
        __syncthreads();

        if (kt * 64 >= warp_cnt) continue;

        float c[8][4];
#pragma unroll
        for (int nt = 0; nt < 8; nt++)
#pragma unroll
            for (int i = 0; i < 4; i++) c[nt][i] = 0.f;
#pragma unroll
        for (int ks = 0; ks < 8; ks++) {
            uint32_t bf[8][2];
#pragma unroll
            for (int nt = 0; nt < 8; nt++) {
                bf[nt][0] = __float_as_uint(Ks[(nt * 8 + gid) * KSTR + ks * 8 + tig]);
                bf[nt][1] = __float_as_uint(Ks[(nt * 8 + gid) * KSTR + ks * 8 + tig + 4]);
            }
#pragma unroll
            for (int nt = 0; nt < 8; nt++)
                mma_tf32(c[nt], aq[ks], bf[nt]);
        }

        float t0 = -1e30f, t1 = -1e30f;
#pragma unroll
        for (int nt = 0; nt < 8; nt++) {
            const int jc = kt * 64 + nt * 8 + 2 * tig;
            c[nt][0] = (jc     < cnt_r0) ? c[nt][0] : -1e30f;
            c[nt][1] = (jc + 1 < cnt_r0) ? c[nt][1] : -1e30f;
            c[nt][2] = (jc     < cnt_r1) ? c[nt][2] : -1e30f;
            c[nt][3] = (jc + 1 < cnt_r1) ? c[nt][3] : -1e30f;
            t0 = fmaxf(t0, fmaxf(c[nt][0], c[nt][1]));
            t1 = fmaxf(t1, fmaxf(c[nt][2], c[nt][3]));
        }
        t0 = fmaxf(t0, __shfl_xor_sync(0xffffffffu, t0, 1));
        t0 = fmaxf(t0, __shfl_xor_sync(0xffffffffu, t0, 2));
        t1 = fmaxf(t1, __shfl_xor_sync(0xffffffffu, t1, 1));
        t1 = fmaxf(t1, __shfl_xor_sync(0xffffffffu, t1, 2));

        const float mn0 = fmaxf(m0, t0), mn1 = fmaxf(m1, t1);
        const float al0 = __expf(m0 - mn0), al1 = __expf(m1 - mn1);
        m0 = mn0; m1 = mn1;

        float rs0 = 0.f, rs1 = 0.f;
#pragma unroll
        for (int nt = 0; nt < 8; nt++) {
            float p0 = rna_tf32(__expf(c[nt][0] - mn0));
            float p1 = rna_tf32(__expf(c[nt][1] - mn0));
            float p2 = rna_tf32(__expf(c[nt][2] - mn1));
            float p3 = rna_tf32(__expf(c[nt][3] - mn1));
            c[nt][0] = p0; c[nt][1] = p1; c[nt][2] = p2; c[nt][3] = p3;
            rs0 += p0 + p1; rs1 += p2 + p3;
        }
        rs0 += __shfl_xor_sync(0xffffffffu, rs0, 1);
        rs0 += __shfl_xor_sync(0xffffffffu, rs0, 2);
        rs1 += __shfl_xor_sync(0xffffffffu, rs1, 1);
        rs1 += __shfl_xor_sync(0xffffffffu, rs1, 2);
        l0 = l0 * al0 + rs0;
        l1 = l1 * al1 + rs1;

#pragma unroll
        for (int nt = 0; nt < 8; nt++) {
            co[nt][0] *= al0; co[nt][1] *= al0;
            co[nt][2] *= al1; co[nt][3] *= al1;
        }

#pragma unroll
        for (int nt = 0; nt < 8; nt++) {
            Ps[r0 * QSTR + nt * 8 + 2 * tig]           = c[nt][0];
            Ps[r0 * QSTR + nt * 8 + 2 * tig + 1]       = c[nt][1];
            Ps[(r0 + 8) * QSTR + nt * 8 + 2 * tig]     = c[nt][2];
            Ps[(r0 + 8) * QSTR + nt * 8 + 2 * tig + 1] = c[nt][3];
        }
        __syncwarp();
#pragma unroll
        for (int ks = 0; ks < 8; ks++) {
            uint32_t ap[4], bf[8][2];
            ap[0] = __float_as_uint(Ps[r0 * QSTR + ks * 8 + tig]);
            ap[1] = __float_as_uint(Ps[(r0 + 8) * QSTR + ks * 8 + tig]);
            ap[2] = __float_as_uint(Ps[r0 * QSTR + ks * 8 + tig + 4]);
            ap[3] = __float_as_uint(Ps[(r0 + 8) * QSTR + ks * 8 + tig + 4]);
#pragma unroll
            for (int nt = 0; nt < 8; nt++) {
                bf[nt][0] = __float_as_uint(Vs[(ks * 8 + tig) * VSTR + nt * 8 + gid]);
                bf[nt][1] = __float_as_uint(Vs[(ks * 8 + tig + 4) * VSTR + nt * 8 + gid]);
            }
#pragma unroll
            for (int nt = 0; nt < 8; nt++)
                mma_tf32(co[nt], ap, bf[nt]);
        }
        __syncwarp();
    }

    const float inv0 = (cnt_r0 > 0) ? (1.f / l0) : 0.f;
    const float inv1 = (cnt_r1 > 0) ? (1.f / l1) : 0.f;
    float* o0 = g_attn + (size_t)(b * SS + q0 + r0) * FFDIM + h * DD;
    float* o1 = g_attn + (size_t)(b * SS + q0 + r0 + 8) * FFDIM + h * DD;
#pragma unroll
    for (int nt = 0; nt < 8; nt++) {
        float2 u0, u1;
        u0.x = co[nt][0] * inv0; u0.y = co[nt][1] * inv0;
        u1.x = co[nt][2] * inv1; u1.y = co[nt][3] * inv1;
        *(float2*)(o0 + nt * 8 + 2 * tig) = u0;
        *(float2*)(o1 + nt * 8 + 2 * tig) = u1;
    }
}

// ============================ launch ============================
extern "C" void kernel_launch(void* const* d_in, const int* in_sizes, int n_in,
                              void* d_out, int out_size)
{
    const float*         x      = (const float*)d_in[0];
    const unsigned char* pmask  = (const unsigned char*)d_in[1];
    const float*         w_qkv  = (const float*)d_in[2];
    const float*         b_qkv  = (const float*)d_in[3];
    const float*         w_out  = (const float*)d_in[4];
    const float*         b_out  = (const float*)d_in[5];
    float*               out    = (float*)d_out;

    float* q = nullptr;
    float* attn = nullptr;
    cudaGetSymbolAddress((void**)&q,    g_q);
    cudaGetSymbolAddress((void**)&attn, g_attn);

    cudaFuncSetAttribute(tf32_mma_gemm<0>,
                         cudaFuncAttributeMaxDynamicSharedMemorySize, GEMM_SMEM);
    cudaFuncSetAttribute(tf32_mma_gemm<1>,
                         cudaFuncAttributeMaxDynamicSharedMemorySize, GEMM_SMEM);
    cudaFuncSetAttribute(tf32_mma_gemm<2>,
                         cudaFuncAttributeMaxDynamicSharedMemorySize, GEMM_SMEM);
    cudaFuncSetAttribute(attn_mma_kernel,
                         cudaFuncAttributeMaxDynamicSharedMemorySize, ATTN_SMEM);

    mask_canon_kernel<<<1, 256>>>(pmask);
    compact_kernel<<<BB, 256>>>();

    // GEMM_Q: x @ w_qkv[:,0:1024] + b_qkv[0:1024] -> g_q
    {
        dim3 grid(FFDIM / 128, MROWS / 128);
        tf32_mma_gemm<0><<<grid, 128, GEMM_SMEM>>>(x, w_qkv, b_qkv, nullptr,
                                                   q, FFDIM, N3, FFDIM);
    }
    // GEMM_KV: compacted-row x @ w_qkv[:,1024:3072] -> g_kc / g_vc (tf32-rounded)
    {
        dim3 grid(2 * FFDIM / 128, MROWS / 128);
        tf32_mma_gemm<2><<<grid, 128, GEMM_SMEM>>>(x, w_qkv + FFDIM, b_qkv + FFDIM,
                                                   nullptr, nullptr, 2 * FFDIM, N3, FFDIM);
    }
    // Attention
    {
        dim3 grid(SS / 64, HH, BB);
        attn_mma_kernel<<<grid, 128, ATTN_SMEM>>>();
    }
    // GEMM2: x + g_attn @ w_out + b_out -> out
    {
        dim3 grid(FFDIM / 128, MROWS / 128);
        tf32_mma_gemm<1><<<grid, 128, GEMM_SMEM>>>(attn, w_out, b_out, x,
                                                   out, FFDIM, FFDIM, FFDIM);
    }
}

// round 11
// speedup vs baseline: 5.2494x; 1.0944x over previous
#include <cuda_runtime.h>
#include <math.h>
#include <cstdint>

// Problem constants
#define BB 2
#define SS 2048
#define FFDIM 1024
#define HH 16
#define DD 64
#define MROWS (BB * SS)      // 4096
#define N3 (3 * FFDIM)       // 3072

// Scratch
__device__ float g_q[(size_t)MROWS * FFDIM];    // Q projection, 16 MB
__device__ float g_attn[(size_t)MROWS * FFDIM]; // attention output, 16 MB
__device__ float g_kc[(size_t)MROWS * FFDIM];   // compacted K (tf32-rounded), 16 MB
__device__ float g_vc[(size_t)MROWS * FFDIM];   // compacted V (tf32-rounded), 16 MB
__device__ unsigned char g_mask[MROWS];
__device__ int g_orig[MROWS];                    // per-batch compacted->orig index
__device__ int g_cnt[MROWS];                     // cnt[q] = #valid keys <= q

// ============================ helpers ============================
__device__ __forceinline__ uint32_t smem_u32(const void* p) {
    uint32_t a;
    asm("{ .reg .u64 t; cvta.to.shared.u64 t, %1; cvt.u32.u64 %0, t; }" : "=r"(a) : "l"(p));
    return a;
}
__device__ __forceinline__ void cp_async16(uint32_t dst, const void* src) {
    asm volatile("cp.async.cg.shared.global [%0], [%1], 16;" :: "r"(dst), "l"(src));
}
#define CP_COMMIT() asm volatile("cp.async.commit_group;" ::: "memory")
#define CP_WAIT2()  asm volatile("cp.async.wait_group 2;" ::: "memory")
#define CP_WAIT1()  asm volatile("cp.async.wait_group 1;" ::: "memory")
#define CP_WAIT0()  asm volatile("cp.async.wait_group 0;" ::: "memory")

__device__ __forceinline__ float rna_tf32(float v) {
    uint32_t o;
    asm("cvt.rna.tf32.f32 %0, %1;" : "=r"(o) : "f"(v));
    return __uint_as_float(o);
}
__device__ __forceinline__ void mma_tf32(float* c, const uint32_t* a, const uint32_t* b) {
    asm volatile(
        "mma.sync.aligned.m16n8k8.row.col.f32.tf32.tf32.f32 "
        "{%0,%1,%2,%3}, {%4,%5,%6,%7}, {%8,%9}, {%0,%1,%2,%3};"
        : "+f"(c[0]), "+f"(c[1]), "+f"(c[2]), "+f"(c[3])
        : "r"(a[0]), "r"(a[1]), "r"(a[2]), "r"(a[3]), "r"(b[0]), "r"(b[1]));
}

// ============================ mask canonicalization ============================
__global__ void mask_canon_kernel(const unsigned char* __restrict__ raw)
{
    __shared__ unsigned s_flags;
    const unsigned* w = (const unsigned*)raw;
    const int tid = threadIdx.x;
    if (tid == 0) s_flags = 0;
    __syncthreads();
    unsigned flags = 0;
    for (int i = tid; i < 1024; i += 256) {
        unsigned v = w[i];
        if (v > 1u) flags |= 1u;
        if (v != 0u && v != 0x3f800000u) flags |= 2u;
    }
    atomicOr(&s_flags, flags);
    __syncthreads();
    const unsigned f = s_flags;
    if (!(f & 1u)) {
        for (int i = tid; i < MROWS; i += 256) g_mask[i] = (w[i] != 0u) ? 1 : 0;
    } else if (!(f & 2u)) {
        const float* fp = (const float*)raw;
        for (int i = tid; i < MROWS; i += 256) g_mask[i] = (fp[i] != 0.f) ? 1 : 0;
    } else {
        for (int i = tid; i < MROWS; i += 256) g_mask[i] = (raw[i] != 0) ? 1 : 0;
    }
}

// ============================ compaction scan ============================
__global__ __launch_bounds__(256) void compact_kernel()
{
    __shared__ int part[256];
    const int b = blockIdx.x, tid = threadIdx.x, base = b * SS;
    int loc[8], s = 0;
#pragma unroll
    for (int i = 0; i < 8; i++) {
        int v = g_mask[base + tid * 8 + i] ? 0 : 1;
        loc[i] = v; s += v;
    }
    part[tid] = s;
    __syncthreads();
    for (int off = 1; off < 256; off <<= 1) {
        int v = (tid >= off) ? part[tid - off] : 0;
        __syncthreads();
        part[tid] += v;
        __syncthreads();
    }
    int run = part[tid] - s;
#pragma unroll
    for (int i = 0; i < 8; i++) {
        run += loc[i];
        g_cnt[base + tid * 8 + i] = run;
        if (loc[i]) g_orig[base + run - 1] = tid * 8 + i;
    }
}

// ============================ GEMM tiling constants ============================
#define BKC 32
#define STAGES 3
#define AS_STRIDE 36
#define BS_STRIDE 132
#define A_STAGE (128 * AS_STRIDE)
#define B_STAGE (BKC * BS_STRIDE)
#define STAGE_FLOATS (A_STAGE + B_STAGE)
#define GEMM_SMEM (STAGES * STAGE_FLOATS * 4)

// ============================ merged QKV projection ============================
// Grid (N3/128=24, MROWS/128=32). Columns [0,1024): Q path (all rows -> g_q).
// Columns [1024,3072): KV path (compacted rows via g_orig -> g_kc/g_vc,
// tf32-rounded epilogue, CTA early-exit past valid count).
__global__ __launch_bounds__(128, 2) void qkv_gemm_kernel(
    const float* __restrict__ A, const float* __restrict__ W,
    const float* __restrict__ bias)
{
    extern __shared__ float sm[];
    __shared__ int rowidx[128];
    const uint32_t smb = smem_u32(sm);
    const int tid  = threadIdx.x;
    const int wid  = tid >> 5;
    const int lane = tid & 31;
    const int gid  = lane >> 2;
    const int tig  = lane & 3;
    const int mbase = (wid & 1) * 64;
    const int nbase = (wid >> 1) * 64;
    const int m0 = blockIdx.y * 128;
    const int n0 = blockIdx.x * 128;
    const bool is_kv = (n0 >= FFDIM);

    int bb = 0, m0loc = m0;
    if (is_kv) {
        bb = m0 / SS;
        m0loc = m0 - bb * SS;
        const int nv = g_cnt[bb * SS + SS - 1];
        if (m0loc >= nv) return;
        int j = m0loc + tid;
        rowidx[tid] = (j < nv) ? g_orig[bb * SS + j] : 0;
        __syncthreads();
    }

    const int arow = tid >> 3, ac4 = tid & 7;
    const int bkr  = tid >> 5, bc4 = tid & 31;
    const float* Bbase = W + n0;

    auto issue_stage = [&](int kc, int buf) {
        uint32_t ab = smb + (uint32_t)(buf * STAGE_FLOATS) * 4u;
#pragma unroll
        for (int it = 0; it < 8; it++) {
            int row = arow + it * 16;
            const float* src = is_kv
                ? A + (size_t)(bb * SS + rowidx[row]) * FFDIM + kc * BKC + ac4 * 4
                : A + (size_t)(m0 + row) * FFDIM + kc * BKC + ac4 * 4;
            cp_async16(ab + (uint32_t)(row * AS_STRIDE + ac4 * 4) * 4u, src);
        }
        const float* Bsrc = Bbase + (size_t)(kc * BKC) * N3;
        uint32_t bbuf = smb + (uint32_t)(buf * STAGE_FLOATS + A_STAGE) * 4u;
#pragma unroll
        for (int it = 0; it < 8; it++) {
            int kr = bkr + it * 4;
            cp_async16(bbuf + (uint32_t)(kr * BS_STRIDE + bc4 * 4) * 4u,
                       Bsrc + (size_t)kr * N3 + bc4 * 4);
        }
    };

    float acc[4][8][4];
#pragma unroll
    for (int i = 0; i < 4; i++)
#pragma unroll
        for (int j = 0; j < 8; j++)
#pragma unroll
            for (int c = 0; c < 4; c++) acc[i][j][c] = 0.f;

    const int nch = FFDIM / BKC;

    issue_stage(0, 0); CP_COMMIT();
    issue_stage(1, 1); CP_COMMIT();

    for (int ch = 0; ch < nch; ch++) {
        if (ch + 2 < nch) issue_stage(ch + 2, (ch + 2) % STAGES);
        CP_COMMIT();
        CP_WAIT2();
        __syncthreads();

        const float* As = sm + (ch % STAGES) * STAGE_FLOATS;
        const float* Bs = As + A_STAGE;
#pragma unroll
        for (int ks = 0; ks < 4; ks++) {
            const int k = ks * 8;
            uint32_t af[4][4], bf[8][2];
#pragma unroll
            for (int mf = 0; mf < 4; mf++) {
                const int r0 = mbase + mf * 16 + gid;
                af[mf][0] = __float_as_uint(As[r0 * AS_STRIDE + k + tig]);
                af[mf][1] = __float_as_uint(As[(r0 + 8) * AS_STRIDE + k + tig]);
                af[mf][2] = __float_as_uint(As[r0 * AS_STRIDE + k + tig + 4]);
                af[mf][3] = __float_as_uint(As[(r0 + 8) * AS_STRIDE + k + tig + 4]);
            }
#pragma unroll
            for (int nf = 0; nf < 8; nf++) {
                const int n = nbase + nf * 8 + gid;
                bf[nf][0] = __float_as_uint(Bs[(k + tig) * BS_STRIDE + n]);
                bf[nf][1] = __float_as_uint(Bs[(k + tig + 4) * BS_STRIDE + n]);
            }
#pragma unroll
            for (int mf = 0; mf < 4; mf++)
#pragma unroll
                for (int nf = 0; nf < 8; nf++)
                    mma_tf32(acc[mf][nf], af[mf], bf[nf]);
        }
        __syncthreads();
    }

    if (is_kv) {
        const int n0k = n0 - FFDIM;
        float* Cb = (n0k < FFDIM) ? (g_kc + n0k) : (g_vc + (n0k - FFDIM));
#pragma unroll
        for (int mf = 0; mf < 4; mf++) {
            const int m = m0loc + mbase + mf * 16 + gid;
            const size_t r0o = (size_t)(bb * SS + m) * FFDIM;
            const size_t r1o = (size_t)(bb * SS + m + 8) * FFDIM;
#pragma unroll
            for (int nf = 0; nf < 8; nf++) {
                const int cl = nbase + nf * 8 + 2 * tig;
                const float b0 = bias[n0 + cl], b1 = bias[n0 + cl + 1];
                float2 v0, v1;
                v0.x = rna_tf32(acc[mf][nf][0] + b0);
                v0.y = rna_tf32(acc[mf][nf][1] + b1);
                v1.x = rna_tf32(acc[mf][nf][2] + b0);
                v1.y = rna_tf32(acc[mf][nf][3] + b1);
                *(float2*)(Cb + r0o + cl) = v0;
                *(float2*)(Cb + r1o + cl) = v1;
            }
        }
    } else {
#pragma unroll
        for (int mf = 0; mf < 4; mf++) {
            const int rr = m0 + mbase + mf * 16 + gid;
#pragma unroll
            for (int nf = 0; nf < 8; nf++) {
                const int cc = n0 + nbase + nf * 8 + 2 * tig;
                const float b0 = bias[cc], b1 = bias[cc + 1];
                size_t o = (size_t)rr * FFDIM + cc;
                size_t o1 = (size_t)(rr + 8) * FFDIM + cc;
                float2 v0, v1;
                v0.x = acc[mf][nf][0] + b0; v0.y = acc[mf][nf][1] + b1;
                v1.x = acc[mf][nf][2] + b0; v1.y = acc[mf][nf][3] + b1;
                *(float2*)(g_q + o)  = v0;
                *(float2*)(g_q + o1) = v1;
            }
        }
    }
}

// ============================ output GEMM (+bias+residual) ============================
__global__ __launch_bounds__(128, 2) void out_gemm_kernel(
    const float* __restrict__ A, const float* __restrict__ W,
    const float* __restrict__ bias, const float* __restrict__ R,
    float* __restrict__ C)
{
    extern __shared__ float sm[];
    const uint32_t smb = smem_u32(sm);
    const int tid  = threadIdx.x;
    const int wid  = tid >> 5;
    const int lane = tid & 31;
    const int gid  = lane >> 2;
    const int tig  = lane & 3;
    const int mbase = (wid & 1) * 64;
    const int nbase = (wid >> 1) * 64;
    const int m0 = blockIdx.y * 128;
    const int n0 = blockIdx.x * 128;

    const int arow = tid >> 3, ac4 = tid & 7;
    const int bkr  = tid >> 5, bc4 = tid & 31;
    const float* Abase = A + (size_t)m0 * FFDIM;
    const float* Bbase = W + n0;

    auto issue_stage = [&](int kc, int buf) {
        uint32_t ab = smb + (uint32_t)(buf * STAGE_FLOATS) * 4u;
#pragma unroll
        for (int it = 0; it < 8; it++) {
            int row = arow + it * 16;
            cp_async16(ab + (uint32_t)(row * AS_STRIDE + ac4 * 4) * 4u,
                       Abase + (size_t)row * FFDIM + kc * BKC + ac4 * 4);
        }
        const float* Bsrc = Bbase + (size_t)(kc * BKC) * FFDIM;
        uint32_t bbuf = smb + (uint32_t)(buf * STAGE_FLOATS + A_STAGE) * 4u;
#pragma unroll
        for (int it = 0; it < 8; it++) {
            int kr = bkr + it * 4;
            cp_async16(bbuf + (uint32_t)(kr * BS_STRIDE + bc4 * 4) * 4u,
                       Bsrc + (size_t)kr * FFDIM + bc4 * 4);
        }
    };

    float acc[4][8][4];
#pragma unroll
    for (int i = 0; i < 4; i++)
#pragma unroll
        for (int j = 0; j < 8; j++)
#pragma unroll
            for (int c = 0; c < 4; c++) acc[i][j][c] = 0.f;

    const int nch = FFDIM / BKC;
    issue_stage(0, 0); CP_COMMIT();
    issue_stage(1, 1); CP_COMMIT();

    for (int ch = 0; ch < nch; ch++) {
        if (ch + 2 < nch) issue_stage(ch + 2, (ch + 2) % STAGES);
        CP_COMMIT();
        CP_WAIT2();
        __syncthreads();

        const float* As = sm + (ch % STAGES) * STAGE_FLOATS;
        const float* Bs = As + A_STAGE;
#pragma unroll
        for (int ks = 0; ks < 4; ks++) {
            const int k = ks * 8;
            uint32_t af[4][4], bf[8][2];
#pragma unroll
            for (int mf = 0; mf < 4; mf++) {
                const int r0 = mbase + mf * 16 + gid;
                af[mf][0] = __float_as_uint(As[r0 * AS_STRIDE + k + tig]);
                af[mf][1] = __float_as_uint(As[(r0 + 8) * AS_STRIDE + k + tig]);
                af[mf][2] = __float_as_uint(As[r0 * AS_STRIDE + k + tig + 4]);
                af[mf][3] = __float_as_uint(As[(r0 + 8) * AS_STRIDE + k + tig + 4]);
            }
#pragma unroll
            for (int nf = 0; nf < 8; nf++) {
                const int n = nbase + nf * 8 + gid;
                bf[nf][0] = __float_as_uint(Bs[(k + tig) * BS_STRIDE + n]);
                bf[nf][1] = __float_as_uint(Bs[(k + tig + 4) * BS_STRIDE + n]);
            }
#pragma unroll
            for (int mf = 0; mf < 4; mf++)
#pragma unroll
                for (int nf = 0; nf < 8; nf++)
                    mma_tf32(acc[mf][nf], af[mf], bf[nf]);
        }
        __syncthreads();
    }

#pragma unroll
    for (int mf = 0; mf < 4; mf++) {
        const int rr = m0 + mbase + mf * 16 + gid;
#pragma unroll
        for (int nf = 0; nf < 8; nf++) {
            const int cc = n0 + nbase + nf * 8 + 2 * tig;
            const float b0 = bias[cc], b1 = bias[cc + 1];
            size_t o0 = (size_t)rr * FFDIM + cc;
            size_t o1 = (size_t)(rr + 8) * FFDIM + cc;
            float2 r0 = *(const float2*)(R + o0);
            float2 r1 = *(const float2*)(R + o1);
            float2 v0, v1;
            v0.x = acc[mf][nf][0] + b0 + r0.x; v0.y = acc[mf][nf][1] + b1 + r0.y;
            v1.x = acc[mf][nf][2] + b0 + r1.x; v1.y = acc[mf][nf][3] + b1 + r1.y;
            *(float2*)(C + o0) = v0;
            *(float2*)(C + o1) = v1;
        }
    }
}

// ============================ flash attention v2 ============================
// cp.async double-buffered K/V; P reuses the (dead) Q smem region.
#define QSTR 68
#define KSTR 68
#define VSTR 72
#define ATTN_K (64 * QSTR)                       // 4352 floats
#define ATTN_V (ATTN_K + 2 * 64 * KSTR)          // 13056
#define ATTN_FLOATS (ATTN_V + 2 * 64 * VSTR)     // 22272
#define ATTN_SMEM (ATTN_FLOATS * 4)              // 89088 bytes

__global__ __launch_bounds__(128) void attn_mma_kernel()
{
    extern __shared__ float sm[];
    const uint32_t smb = smem_u32(sm);
    float* Qs = sm;        // doubles as Ps after fragment extraction

    const int qb  = (int)gridDim.x - 1 - (int)blockIdx.x;
    const int h   = blockIdx.y;
    const int b   = blockIdx.z;
    const int tid = threadIdx.x;
    const int w   = tid >> 5;
    const int lane = tid & 31;
    const int gid = lane >> 2;
    const int tig = lane & 3;
    const int q0 = qb * 64;

    // Stage Q (pre-scaled by 1/sqrt(D), tf32-rounded)
#pragma unroll
    for (int it = 0; it < 8; it++) {
        int idx = it * 128 + tid;
        int row = idx >> 4, c4 = idx & 15;
        float4 v = *(const float4*)(g_q + (size_t)(b * SS + q0 + row) * FFDIM + h * DD + c4 * 4);
        v.x = rna_tf32(v.x * 0.125f); v.y = rna_tf32(v.y * 0.125f);
        v.z = rna_tf32(v.z * 0.125f); v.w = rna_tf32(v.w * 0.125f);
        *(float4*)&Qs[row * QSTR + c4 * 4] = v;
    }
    __syncthreads();

    const int r0 = w * 16 + gid;
    uint32_t aq[8][4];
#pragma unroll
    for (int ks = 0; ks < 8; ks++) {
        aq[ks][0] = __float_as_uint(Qs[r0 * QSTR + ks * 8 + tig]);
        aq[ks][1] = __float_as_uint(Qs[(r0 + 8) * QSTR + ks * 8 + tig]);
        aq[ks][2] = __float_as_uint(Qs[r0 * QSTR + ks * 8 + tig + 4]);
        aq[ks][3] = __float_as_uint(Qs[(r0 + 8) * QSTR + ks * 8 + tig + 4]);
    }

    const int cnt_r0   = g_cnt[b * SS + q0 + w * 16 + gid];
    const int cnt_r1   = g_cnt[b * SS + q0 + w * 16 + gid + 8];
    const int warp_cnt = g_cnt[b * SS + q0 + w * 16 + 15];
    const int nkeys    = g_cnt[b * SS + q0 + 63];
    const int ntiles   = (nkeys + 63) >> 6;

    auto issue_kv = [&](int kt) {
        const int buf = kt & 1;
        uint32_t kb = smb + (uint32_t)(ATTN_K + buf * 64 * KSTR) * 4u;
        uint32_t vb = smb + (uint32_t)(ATTN_V + buf * 64 * VSTR) * 4u;
#pragma unroll
        for (int it = 0; it < 8; it++) {
            int idx = it * 128 + tid;
            int row = idx >> 4, c4 = idx & 15;
            size_t g = (size_t)(b * SS + kt * 64 + row) * FFDIM + h * DD + c4 * 4;
            cp_async16(kb + (uint32_t)(row * KSTR + c4 * 4) * 4u, g_kc + g);
            cp_async16(vb + (uint32_t)(row * VSTR + c4 * 4) * 4u, g_vc + g);
        }
    };

    float m0 = -1e30f, m1 = -1e30f, l0 = 0.f, l1 = 0.f;
    float co[8][4];
#pragma unroll
    for (int nt = 0; nt < 8; nt++)
#pragma unroll
        for (int i = 0; i < 4; i++) co[nt][i] = 0.f;

    if (ntiles > 0) { issue_kv(0); CP_COMMIT(); }

    for (int kt = 0; kt < ntiles; kt++) {
        if (kt + 1 < ntiles) { issue_kv(kt + 1); CP_COMMIT(); CP_WAIT1(); }
        else { CP_WAIT0(); }
        __syncthreads();

        if (kt * 64 < warp_cnt) {
            const float* Ks = sm + ATTN_K + (kt & 1) * 64 * KSTR;
            const float* Vs = sm + ATTN_V + (kt & 1) * 64 * VSTR;

            float c[8][4];
#pragma unroll
            for (int nt = 0; nt < 8; nt++)
#pragma unroll
                for (int i = 0; i < 4; i++) c[nt][i] = 0.f;
#pragma unroll
            for (int ks = 0; ks < 8; ks++) {
                uint32_t bf[8][2];
#pragma unroll
                for (int nt = 0; nt < 8; nt++) {
                    bf[nt][0] = __float_as_uint(Ks[(nt * 8 + gid) * KSTR + ks * 8 + tig]);
                    bf[nt][1] = __float_as_uint(Ks[(nt * 8 + gid) * KSTR + ks * 8 + tig + 4]);
                }
#pragma unroll
                for (int nt = 0; nt < 8; nt++)
                    mma_tf32(c[nt], aq[ks], bf[nt]);
            }

            float t0 = -1e30f, t1 = -1e30f;
#pragma unroll
            for (int nt = 0; nt < 8; nt++) {
                const int jc = kt * 64 + nt * 8 + 2 * tig;
                c[nt][0] = (jc     < cnt_r0) ? c[nt][0] : -1e30f;
                c[nt][1] = (jc + 1 < cnt_r0) ? c[nt][1] : -1e30f;
                c[nt][2] = (jc     < cnt_r1) ? c[nt][2] : -1e30f;
                c[nt][3] = (jc + 1 < cnt_r1) ? c[nt][3] : -1e30f;
                t0 = fmaxf(t0, fmaxf(c[nt][0], c[nt][1]));
                t1 = fmaxf(t1, fmaxf(c[nt][2], c[nt][3]));
            }
            t0 = fmaxf(t0, __shfl_xor_sync(0xffffffffu, t0, 1));
            t0 = fmaxf(t0, __shfl_xor_sync(0xffffffffu, t0, 2));
            t1 = fmaxf(t1, __shfl_xor_sync(0xffffffffu, t1, 1));
            t1 = fmaxf(t1, __shfl_xor_sync(0xffffffffu, t1, 2));

            const float mn0 = fmaxf(m0, t0), mn1 = fmaxf(m1, t1);
            const float al0 = __expf(m0 - mn0), al1 = __expf(m1 - mn1);
            m0 = mn0; m1 = mn1;

            float rs0 = 0.f, rs1 = 0.f;
#pragma unroll
            for (int nt = 0; nt < 8; nt++) {
                float p0 = rna_tf32(__expf(c[nt][0] - mn0));
                float p1 = rna_tf32(__expf(c[nt][1] - mn0));
                float p2 = rna_tf32(__expf(c[nt][2] - mn1));
                float p3 = rna_tf32(__expf(c[nt][3] - mn1));
                c[nt][0] = p0; c[nt][1] = p1; c[nt][2] = p2; c[nt][3] = p3;
                rs0 += p0 + p1; rs1 += p2 + p3;
            }
            rs0 += __shfl_xor_sync(0xffffffffu, rs0, 1);
            rs0 += __shfl_xor_sync(0xffffffffu, rs0, 2);
            rs1 += __shfl_xor_sync(0xffffffffu, rs1, 1);
            rs1 += __shfl_xor_sync(0xffffffffu, rs1, 2);
            l0 = l0 * al0 + rs0;
            l1 = l1 * al1 + rs1;

#pragma unroll
            for (int nt = 0; nt < 8; nt++) {
                co[nt][0] *= al0; co[nt][1] *= al0;
                co[nt][2] *= al1; co[nt][3] *= al1;
            }

            // P -> warp-private rows of the (dead) Q region
#pragma unroll
            for (int nt = 0; nt < 8; nt++) {
                Qs[r0 * QSTR + nt * 8 + 2 * tig]           = c[nt][0];
                Qs[r0 * QSTR + nt * 8 + 2 * tig + 1]       = c[nt][1];
                Qs[(r0 + 8) * QSTR + nt * 8 + 2 * tig]     = c[nt][2];
                Qs[(r0 + 8) * QSTR + nt * 8 + 2 * tig + 1] = c[nt][3];
            }
            __syncwarp();
#pragma unroll
            for (int ks = 0; ks < 8; ks++) {
                uint32_t ap[4], bf[8][2];
                ap[0] = __float_as_uint(Qs[r0 * QSTR + ks * 8 + tig]);
                ap[1] = __float_as_uint(Qs[(r0 + 8) * QSTR + ks * 8 + tig]);
                ap[2] = __float_as_uint(Qs[r0 * QSTR + ks * 8 + tig + 4]);
                ap[3] = __float_as_uint(Qs[(r0 + 8) * QSTR + ks * 8 + tig + 4]);
#pragma unroll
                for (int nt = 0; nt < 8; nt++) {
                    bf[nt][0] = __float_as_uint(Vs[(ks * 8 + tig) * VSTR + nt * 8 + gid]);
                    bf[nt][1] = __float_as_uint(Vs[(ks * 8 + tig + 4) * VSTR + nt * 8 + gid]);
                }
#pragma unroll
                for (int nt = 0; nt < 8; nt++)
                    mma_tf32(co[nt], ap, bf[nt]);
            }
            __syncwarp();
        }
        __syncthreads();
    }

    const float inv0 = (cnt_r0 > 0) ? (1.f / l0) : 0.f;
    const float inv1 = (cnt_r1 > 0) ? (1.f / l1) : 0.f;
    float* o0 = g_attn + (size_t)(b * SS + q0 + r0) * FFDIM + h * DD;
    float* o1 = g_attn + (size_t)(b * SS + q0 + r0 + 8) * FFDIM + h * DD;
#pragma unroll
    for (int nt = 0; nt < 8; nt++) {
        float2 u0, u1;
        u0.x = co[nt][0] * inv0; u0.y = co[nt][1] * inv0;
        u1.x = co[nt][2] * inv1; u1.y = co[nt][3] * inv1;
        *(float2*)(o0 + nt * 8 + 2 * tig) = u0;
        *(float2*)(o1 + nt * 8 + 2 * tig) = u1;
    }
}

// ============================ launch ============================
extern "C" void kernel_launch(void* const* d_in, const int* in_sizes, int n_in,
                              void* d_out, int out_size)
{
    const float*         x      = (const float*)d_in[0];
    const unsigned char* pmask  = (const unsigned char*)d_in[1];
    const float*         w_qkv  = (const float*)d_in[2];
    const float*         b_qkv  = (const float*)d_in[3];
    const float*         w_out  = (const float*)d_in[4];
    const float*         b_out  = (const float*)d_in[5];
    float*               out    = (float*)d_out;

    float* attn = nullptr;
    cudaGetSymbolAddress((void**)&attn, g_attn);

    cudaFuncSetAttribute(qkv_gemm_kernel,
                         cudaFuncAttributeMaxDynamicSharedMemorySize, GEMM_SMEM);
    cudaFuncSetAttribute(out_gemm_kernel,
                         cudaFuncAttributeMaxDynamicSharedMemorySize, GEMM_SMEM);
    cudaFuncSetAttribute(attn_mma_kernel,
                         cudaFuncAttributeMaxDynamicSharedMemorySize, ATTN_SMEM);

    mask_canon_kernel<<<1, 256>>>(pmask);
    compact_kernel<<<BB, 256>>>();

    // Merged QKV projection
    {
        dim3 grid(N3 / 128, MROWS / 128);
        qkv_gemm_kernel<<<grid, 128, GEMM_SMEM>>>(x, w_qkv, b_qkv);
    }
    // Attention
    {
        dim3 grid(SS / 64, HH, BB);
        attn_mma_kernel<<<grid, 128, ATTN_SMEM>>>();
    }
    // Output projection + residual
    {
        dim3 grid(FFDIM / 128, MROWS / 128);
        out_gemm_kernel<<<grid, 128, GEMM_SMEM>>>(attn, w_out, b_out, x, out);
    }
}